// round 13
// baseline (speedup 1.0000x reference)
#include <cuda_runtime.h>
#include <cuda_bf16.h>
#include <math.h>

// ---------------- device scratch (no allocations allowed) ----------------
__device__ __nv_bfloat16 g_Wb[33 * 64 * 64]; // [k][d][e]; slot 32 = U (cross)
__device__ float g_nhc[32];                  // -0.5*(D*log2pi + logdet + tau)
__device__ float g_part[4096];               // per-block partial sums
__device__ int   g_ready;                    // # components prepped
__device__ int   g_done;                     // # blocks finished

#define LOG2PI 1.8378770664093453f
#define SW 72    // bf16 smem row stride: conflict-free fragment LDS
#define PSW 36   // Ps float stride: 144B rows (16B-aligned for cp.async)

// dynamic smem layout (bytes). Prep overlays [0, ~34KB) inside Xs region.
#define OFF_XS   0                          // bf16 [256*SW]            36864
#define OFF_WS   36864                      // bf16 [3][64*SW]          27648
#define OFF_PS   64512                      // float [256*PSW]          36864
#define OFF_NHC  101376                     // float [32]                 128
#define OFF_LBL  101504                     // int   [256]               1024
#define OFF_RED  102528                     // float [256]               1024
#define OFF_FLG  103552                     // int                         16
#define SMEM_TOTAL 103568

__device__ __forceinline__ void cp_async16(void* dst, const void* src) {
    unsigned a = (unsigned)__cvta_generic_to_shared(dst);
    asm volatile("cp.async.ca.shared.global [%0], [%1], 16;\n" :: "r"(a), "l"(src));
}

#define MMA(c0,c1,c2,c3,a0,a1,a2,a3,b0,b1)                                   \
    asm volatile(                                                            \
        "mma.sync.aligned.m16n8k16.row.col.f32.bf16.bf16.f32 "               \
        "{%0,%1,%2,%3}, {%4,%5,%6,%7}, {%8,%9}, {%0,%1,%2,%3};\n"            \
        : "+f"(c0), "+f"(c1), "+f"(c2), "+f"(c3)                             \
        : "r"(a0), "r"(a1), "r"(a2), "r"(a3), "r"(b0), "r"(b1))

// ---------------- prep (device fn, 256 threads) -------------------------------
__device__ void do_prep(int k, const float* __restrict__ cov,
                        const float* __restrict__ cen, char* smem_raw, int tid)
{
    float* A    = (float*)smem_raw;          // 64*65
    float* Li   = A  + 64 * 65;              // 64*65
    float* rd   = Li + 64 * 65;              // 64
    float* dl   = rd + 64;                   // 64
    float* tsm  = dl + 64;                   // 64

    const int l = tid & 31;

    for (int idx = tid; idx < 4096; idx += 256)
        A[(idx >> 6) * 65 + (idx & 63)] = cov[k * 4096 + idx];
    __syncthreads();

    // blocked right-looking Cholesky: 8 panels of 8 columns
    #pragma unroll 1
    for (int p = 0; p < 8; ++p) {
        const int c0 = p * 8;
        if (tid < 32) {                       // panel: warp 0, register-resident
            const int r0 = c0 + l, r1 = c0 + 32 + l;
            const bool act0 = (r0 < 64), act1 = (r1 < 64);
            float a0[8], a1[8];
            #pragma unroll
            for (int m = 0; m < 8; ++m) {
                a0[m] = act0 ? A[r0 * 65 + c0 + m] : 0.f;
                a1[m] = act1 ? A[r1 * 65 + c0 + m] : 0.f;
            }
            #pragma unroll
            for (int jj = 0; jj < 8; ++jj) {
                const float d = __shfl_sync(0xffffffffu, a0[jj], jj);
                const float rs = rsqrtf(d);
                if (act0 && l >= jj) a0[jj] *= rs;
                if (act1)            a1[jj] *= rs;
                float lv[8];
                #pragma unroll
                for (int m = jj + 1; m < 8; ++m)
                    lv[m] = __shfl_sync(0xffffffffu, a0[jj], m);
                #pragma unroll
                for (int m = jj + 1; m < 8; ++m) {
                    if (act0 && l > jj) a0[m] -= a0[jj] * lv[m];
                    if (act1)           a1[m] -= a1[jj] * lv[m];
                }
            }
            #pragma unroll
            for (int m = 0; m < 8; ++m) {
                if (act0) A[r0 * 65 + c0 + m] = a0[m];
                if (act1) A[r1 * 65 + c0 + m] = a1[m];
            }
        }
        __syncthreads();
        // trailing rank-8 update, lower triangle only; 256 threads
        const int R = 56 - c0;
        if (R > 0) {
            const int rr = tid >> 2, cq = tid & 3;
            if (rr < R) {
                const int r = c0 + 8 + rr;
                float pr[8];
                #pragma unroll
                for (int m = 0; m < 8; ++m) pr[m] = A[r * 65 + c0 + m];
                #pragma unroll 4
                for (int cc = cq; cc <= rr; cc += 4) {
                    const int c = c0 + 8 + cc;
                    float s0 = A[r * 65 + c], s1 = 0.f;
                    #pragma unroll
                    for (int m = 0; m < 4; ++m) {
                        s0 -= pr[m]     * A[c * 65 + c0 + m];
                        s1 += pr[m + 4] * A[c * 65 + c0 + m + 4];
                    }
                    A[r * 65 + c] = s0 - s1;
                }
            }
        }
        __syncthreads();
    }

    if (tid < 64) {
        const float dii = A[tid * 65 + tid];
        dl[tid] = 2.f * logf(dii);
        rd[tid] = 1.0f / dii;
    }
    __syncthreads();

    // forward substitution: 8 warps x 8 columns each
    {
        const int w = tid >> 5;
        const int r0 = l, r1 = l + 32;
        const int c0 = w * 8;
        float v0[8], v1[8];
        #pragma unroll
        for (int j = 0; j < 8; ++j) {
            v0[j] = (r0 == c0 + j) ? 1.f : 0.f;
            v1[j] = (r1 == c0 + j) ? 1.f : 0.f;
        }
        for (int m = 0; m < 64; ++m) {
            const float lr0 = (r0 > m) ? A[r0 * 65 + m] : 0.f;
            const float lr1 = (r1 > m) ? A[r1 * 65 + m] : 0.f;
            const float rdm = rd[m];
            const int   src = m & 31;
            const bool  lo  = (m < 32);
            #pragma unroll
            for (int j = 0; j < 8; ++j) {
                const float resid = lo ? v0[j] : v1[j];
                const float ym = __shfl_sync(0xffffffffu, resid, src) * rdm;
                v0[j] -= lr0 * ym;
                v1[j] -= lr1 * ym;
                if (l == src) Li[m * 65 + c0 + j] = ym;
            }
        }
    }
    __syncthreads();

    // t = Linv * c (fp32), 4-way partials
    if (tid < 64) {
        float s0 = 0.f, s1 = 0.f, s2 = 0.f, s3 = 0.f;
        int e = 0;
        for (; e + 3 <= tid; e += 4) {
            s0 += Li[tid * 65 + e]     * cen[k * 64 + e];
            s1 += Li[tid * 65 + e + 1] * cen[k * 64 + e + 1];
            s2 += Li[tid * 65 + e + 2] * cen[k * 64 + e + 2];
            s3 += Li[tid * 65 + e + 3] * cen[k * 64 + e + 3];
        }
        for (; e <= tid; ++e) s0 += Li[tid * 65 + e] * cen[k * 64 + e];
        tsm[tid] = (s0 + s1) + (s2 + s3);
    }
    __syncthreads();

    // u = Linv^T t (row k of the cross matrix, bf16), 4-way partials
    if (tid < 64) {
        const int e = tid;
        float s0 = 0.f, s1 = 0.f, s2 = 0.f, s3 = 0.f;
        int d = e;
        for (; d + 3 < 64; d += 4) {
            s0 += Li[d * 65 + e]       * tsm[d];
            s1 += Li[(d + 1) * 65 + e] * tsm[d + 1];
            s2 += Li[(d + 2) * 65 + e] * tsm[d + 2];
            s3 += Li[(d + 3) * 65 + e] * tsm[d + 3];
        }
        for (; d < 64; ++d) s0 += Li[d * 65 + e] * tsm[d];
        g_Wb[32 * 4096 + k * 64 + e] = __float2bfloat16_rn((s0 + s1) + (s2 + s3));
    }
    if (tid == 0) {
        float ld = 0.f, tau = 0.f;
        #pragma unroll 4
        for (int m = 0; m < 64; ++m) { ld += dl[m]; tau += tsm[m] * tsm[m]; }
        g_nhc[k] = -0.5f * (64.f * LOG2PI + ld + tau);
    }
    // bf16 W
    #pragma unroll 4
    for (int idx = tid; idx < 4096; idx += 256) {
        const int d = idx >> 6, e = idx & 63;
        const float v = (e <= d) ? Li[d * 65 + e] : 0.f;
        g_Wb[k * 4096 + idx] = __float2bfloat16_rn(v);
    }
}

// ---------------- single fused kernel -----------------------------------------
// grid = 32 prep blocks + B/256 GEMM blocks; block = 256 threads (8 warps)
__global__ void __launch_bounds__(256, 2) fused_kernel(const float* __restrict__ emb,
                                                       const float* __restrict__ cen,
                                                       const float* __restrict__ cov,
                                                       const float* __restrict__ pi,
                                                       const int* __restrict__ labels,
                                                       float* __restrict__ out)
{
    extern __shared__ char smem[];
    __nv_bfloat16* Xs  = (__nv_bfloat16*)(smem + OFF_XS);
    __nv_bfloat16* Ws  = (__nv_bfloat16*)(smem + OFF_WS);   // [3][64*SW]
    float* Ps  = (float*)(smem + OFF_PS);
    float* nhc = (float*)(smem + OFF_NHC);
    int*   lbl = (int*)  (smem + OFF_LBL);
    float* red = (float*)(smem + OFF_RED);
    int*   flg = (int*)  (smem + OFF_FLG);

    const int tid   = threadIdx.x;
    const int total = gridDim.x;         // nb + 32
    const int nb    = total - 32;

    // =================== prep blocks: prep only, then exit =====================
    if (blockIdx.x < 32) {
        do_prep(blockIdx.x, cov, cen, smem, tid);
        __syncthreads();
        if (tid == 0) {
            __threadfence();
            atomicAdd(&g_ready, 1);
            __threadfence();
            const int old = atomicAdd(&g_done, 1);
            flg[0] = (old == total - 1) ? 1 : 0;
        }
        __syncthreads();
        if (flg[0]) {                    // defensive: never last in practice
            __threadfence();
            float a = 0.f;
            for (int i = tid; i < nb; i += 256) a += g_part[i];
            red[tid] = a;
            __syncthreads();
            #pragma unroll
            for (int st = 128; st > 0; st >>= 1) {
                if (tid < st) red[tid] += red[tid + st];
                __syncthreads();
            }
            if (tid == 0) { out[0] = fabsf(red[0]); g_done = 0; g_ready = 0; }
        }
        return;
    }

    // =================== GEMM blocks ==========================================
    const int gbid = blockIdx.x - 32;
    const int b0   = gbid * 256;

    lbl[tid] = labels[b0 + tid];
    __syncthreads();

    // ---- pi gather via cp.async (completion folded into k=0 wait)
    {
        #pragma unroll
        for (int it = 0; it < 8; ++it) {
            const int idx = tid + it * 256;
            const int row = idx >> 3, c8 = idx & 7;
            cp_async16(&Ps[row * PSW + c8 * 4],
                       pi + (size_t)lbl[row] * 32 + c8 * 4);
        }
    }
    asm volatile("cp.async.commit_group;\n");

    // ---- emb gather -> bf16 Xs (overlaps prep blocks' work)
    {
        const int f4 = tid & 15, rg = tid >> 4;
        #pragma unroll 8
        for (int it = 0; it < 16; ++it) {
            const int row = rg + it * 16;
            const float4 v = *(const float4*)(emb + (size_t)lbl[row] * 64 + f4 * 4);
            __nv_bfloat162* p = (__nv_bfloat162*)&Xs[row * SW + f4 * 4];
            p[0] = __nv_bfloat162(__float2bfloat16_rn(v.x), __float2bfloat16_rn(v.y));
            p[1] = __nv_bfloat162(__float2bfloat16_rn(v.z), __float2bfloat16_rn(v.w));
        }
    }
    __syncthreads();   // Xs visible block-wide

    const int w    = tid >> 5;        // warp 0..7 -> rows w*32 .. w*32+31
    const int lane = tid & 31;
    const int g    = lane >> 2;
    const int t4   = lane & 3;
    const int base = w * 32;

    // A fragments: loaded ONCE, live across the whole k loop (32 regs)
    unsigned aF[4][2][4];
    #pragma unroll
    for (int es = 0; es < 4; ++es) {
        const int e0 = es * 16 + 2 * t4;
        #pragma unroll
        for (int rg = 0; rg < 2; ++rg) {
            const int r = base + rg * 16 + g;
            aF[es][rg][0] = *(const unsigned*)&Xs[r       * SW + e0];
            aF[es][rg][1] = *(const unsigned*)&Xs[(r + 8) * SW + e0];
            aF[es][rg][2] = *(const unsigned*)&Xs[r       * SW + e0 + 8];
            aF[es][rg][3] = *(const unsigned*)&Xs[(r + 8) * SW + e0 + 8];
        }
    }

    // ---- wait for all components (cheap volatile poll)
    if (tid == 0) {
        while (*(volatile int*)&g_ready < 32) { __nanosleep(100); }
    }
    __syncthreads();
    __threadfence();
    if (tid < 32) nhc[tid] = g_nhc[tid];

    auto prefetch = [&](int k, int slot) {
        const uint4* src = (const uint4*)(g_Wb + k * 4096);
        #pragma unroll
        for (int it = 0; it < 2; ++it) {
            const int idx = tid + it * 256;
            cp_async16(&Ws[slot * 64 * SW + (idx >> 3) * SW + (idx & 7) * 8],
                       &src[idx]);
        }
    };

    prefetch(0, 0);
    asm volatile("cp.async.commit_group;\n");
    prefetch(1, 1);
    asm volatile("cp.async.commit_group;\n");

    // 4 independent square-term accumulators + 2 cross accumulators
    float accs[2][2];
    #pragma unroll
    for (int rg = 0; rg < 2; ++rg) { accs[rg][0] = 0.f; accs[rg][1] = 0.f; }
    float accc[2] = {0.f, 0.f};

    // ---- main loop: ONE barrier per iteration, 3-slot ring; k=32 is U/cross
    #pragma unroll 1
    for (int k = 0; k <= 32; ++k) {
        asm volatile("cp.async.wait_group 1;\n");   // group k landed
        __syncthreads();                            // visible + slot (k+2)%3 free
        if (k + 2 <= 32) prefetch(k + 2, (k + 2) % 3);
        asm volatile("cp.async.commit_group;\n");   // (empty group ok)

        const __nv_bfloat16* Wk = Ws + (k % 3) * 64 * SW;

        if (k < 32) {
            // raw quad partials this k (p applied once after the j-loop)
            float q0[2] = {0.f, 0.f};
            float q1[2] = {0.f, 0.f};

            #pragma unroll
            for (int j = 0; j < 8; ++j) {
                float c0[2], c1[2], c2[2], c3[2];
                #pragma unroll
                for (int rg = 0; rg < 2; ++rg) { c0[rg]=0.f; c1[rg]=0.f; c2[rg]=0.f; c3[rg]=0.f; }
                // lower-triangular W: rows d in [8j, 8j+8) need only e <= 8j+7
                const int esn = j / 2 + 1;
                #pragma unroll
                for (int es = 0; es < esn; ++es) {
                    const int e0 = es * 16 + 2 * t4;
                    const unsigned b0v = *(const unsigned*)&Wk[(j * 8 + g) * SW + e0];
                    const unsigned b1v = *(const unsigned*)&Wk[(j * 8 + g) * SW + e0 + 8];
                    #pragma unroll
                    for (int rg = 0; rg < 2; ++rg)
                        MMA(c0[rg], c1[rg], c2[rg], c3[rg],
                            aF[es][rg][0], aF[es][rg][1], aF[es][rg][2], aF[es][rg][3],
                            b0v, b1v);
                }
                #pragma unroll
                for (int rg = 0; rg < 2; ++rg) {
                    q0[rg] = fmaf(c0[rg], c0[rg], q0[rg]);
                    q0[rg] = fmaf(c1[rg], c1[rg], q0[rg]);
                    q1[rg] = fmaf(c2[rg], c2[rg], q1[rg]);
                    q1[rg] = fmaf(c3[rg], c3[rg], q1[rg]);
                }
            }
            #pragma unroll
            for (int rg = 0; rg < 2; ++rg) {
                const int r = base + rg * 16 + g;
                accs[rg][0] = fmaf(Ps[r       * PSW + k], q0[rg], accs[rg][0]);
                accs[rg][1] = fmaf(Ps[(r + 8) * PSW + k], q1[rg], accs[rg][1]);
            }
        } else {
            // cross terms: cross[b][k'] = x_b . u_k'  (U dense)
            #pragma unroll
            for (int j = 0; j < 4; ++j) {          // k' = j*8 .. j*8+7
                float c0[2], c1[2], c2[2], c3[2];
                #pragma unroll
                for (int rg = 0; rg < 2; ++rg) { c0[rg]=0.f; c1[rg]=0.f; c2[rg]=0.f; c3[rg]=0.f; }
                #pragma unroll
                for (int es = 0; es < 4; ++es) {
                    const int e0 = es * 16 + 2 * t4;
                    const unsigned b0v = *(const unsigned*)&Wk[(j * 8 + g) * SW + e0];
                    const unsigned b1v = *(const unsigned*)&Wk[(j * 8 + g) * SW + e0 + 8];
                    #pragma unroll
                    for (int rg = 0; rg < 2; ++rg)
                        MMA(c0[rg], c1[rg], c2[rg], c3[rg],
                            aF[es][rg][0], aF[es][rg][1], aF[es][rg][2], aF[es][rg][3],
                            b0v, b1v);
                }
                const int k0 = j * 8 + 2 * t4;
                #pragma unroll
                for (int rg = 0; rg < 2; ++rg) {
                    const int r = base + rg * 16 + g;
                    float cc;
                    cc = fmaf(Ps[r       * PSW + k0],     c0[rg],
                         fmaf(Ps[r       * PSW + k0 + 1], c1[rg], 0.f));
                    cc = fmaf(Ps[(r + 8) * PSW + k0],     c2[rg], cc);
                    cc = fmaf(Ps[(r + 8) * PSW + k0 + 1], c3[rg], cc);
                    accc[rg] += cc;
                }
            }
        }
    }

    // deterministic combine of private partials
    float acc_sq = (accs[0][0] + accs[0][1]) + (accs[1][0] + accs[1][1]);
    float acc_cr = accc[0] + accc[1];
    float acc = fmaf(-0.5f, acc_sq, acc_cr);

    // constant part: row tid
    {
        float c = 0.f;
        #pragma unroll
        for (int kk = 0; kk < 32; ++kk)
            c = fmaf(Ps[tid * PSW + kk], nhc[kk], c);
        acc += c;
    }

    // deterministic block reduction
    red[tid] = acc;
    __syncthreads();
    #pragma unroll
    for (int st = 128; st > 0; st >>= 1) {
        if (tid < st) red[tid] += red[tid + st];
        __syncthreads();
    }
    if (tid == 0) g_part[gbid] = red[0];

    // ---- last block overall: final reduce + reset
    if (tid == 0) {
        __threadfence();
        const int old = atomicAdd(&g_done, 1);
        flg[0] = (old == total - 1) ? 1 : 0;
    }
    __syncthreads();
    if (flg[0]) {
        __threadfence();
        float a = 0.f;
        for (int i = tid; i < nb; i += 256) a += g_part[i];
        red[tid] = a;
        __syncthreads();
        #pragma unroll
        for (int st = 128; st > 0; st >>= 1) {
            if (tid < st) red[tid] += red[tid + st];
            __syncthreads();
        }
        if (tid == 0) {
            out[0] = fabsf(red[0]);
            g_done  = 0;
            g_ready = 0;
        }
    }
}

// ---------------- launch ----------------
extern "C" void kernel_launch(void* const* d_in, const int* in_sizes, int n_in,
                              void* d_out, int out_size)
{
    const float* emb    = (const float*)d_in[0];   // (500000, 64)
    const float* cen    = (const float*)d_in[1];   // (32, 64)
    const float* cov    = (const float*)d_in[2];   // (32, 64, 64)
    const float* pi     = (const float*)d_in[3];   // (500000, 32)
    const int*   labels = (const int*)d_in[4];     // (B,)
    const int B  = in_sizes[4];
    const int nb = B / 256;

    static int configured = 0;
    if (!configured) {
        cudaFuncSetAttribute(fused_kernel, cudaFuncAttributeMaxDynamicSharedMemorySize,
                             SMEM_TOTAL);
        configured = 1;
    }

    fused_kernel<<<nb + 32, 256, SMEM_TOTAL>>>(emb, cen, cov, pi, labels,
                                               (float*)d_out);
}

// round 14
// speedup vs baseline: 1.0141x; 1.0141x over previous
#include <cuda_runtime.h>
#include <cuda_bf16.h>
#include <math.h>

// ---------------- device scratch (no allocations allowed) ----------------
__device__ __nv_bfloat16 g_Wb[33 * 64 * 64]; // [k][d][e]; slot 32 = U (cross)
__device__ float g_nhc[32];                  // -0.5*(D*log2pi + logdet + tau)
__device__ float g_part[4096];               // per-block partial sums
__device__ int   g_ready;                    // # components prepped
__device__ int   g_done;                     // # blocks finished

#define LOG2PI 1.8378770664093453f
#define SW 72    // bf16 smem row stride: conflict-free fragment LDS
#define PSW 36   // Ps float stride: 144B rows (16B-aligned for cp.async)
#define SLOT 4608  // bf16 elems per W slot (64*SW)

// dynamic smem layout (bytes).
// [0, 73728): W ring, 8 slots of 9216B. The FRONT phase overlays Xs
// (256*SW bf16 = 36864B) on slots 0-3; Xs is dead once aF regs are loaded,
// and the first W prefetch is issued only after the post-aF __syncthreads.
// Prep blocks overlay their Cholesky workspace here too (~34KB).
#define OFF_XS   0
#define OFF_WS   0
#define OFF_PS   73728                      // float [256*PSW]          36864
#define OFF_NHC  110592                     // float [32]                 128
#define OFF_LBL  110720                     // int   [256]               1024
#define OFF_RED  111744                     // float [128]                512
#define OFF_FLG  112256                     // int                         16
#define SMEM_TOTAL 112272

__device__ __forceinline__ void cp_async16(void* dst, const void* src) {
    unsigned a = (unsigned)__cvta_generic_to_shared(dst);
    asm volatile("cp.async.ca.shared.global [%0], [%1], 16;\n"
                 :: "r"(a), "l"(src) : "memory");
}

#define MMA(c0,c1,c2,c3,a0,a1,a2,a3,b0,b1)                                   \
    asm volatile(                                                            \
        "mma.sync.aligned.m16n8k16.row.col.f32.bf16.bf16.f32 "               \
        "{%0,%1,%2,%3}, {%4,%5,%6,%7}, {%8,%9}, {%0,%1,%2,%3};\n"            \
        : "+f"(c0), "+f"(c1), "+f"(c2), "+f"(c3)                             \
        : "r"(a0), "r"(a1), "r"(a2), "r"(a3), "r"(b0), "r"(b1))

// ---------------- prep (device fn, 128 threads) -------------------------------
__device__ void do_prep(int k, const float* __restrict__ cov,
                        const float* __restrict__ cen, char* smem_raw, int tid)
{
    float* A    = (float*)smem_raw;          // 64*65
    float* Li   = A  + 64 * 65;              // 64*65
    float* rd   = Li + 64 * 65;              // 64
    float* dl   = rd + 64;                   // 64
    float* tsm  = dl + 64;                   // 64

    const int l = tid & 31;

    for (int idx = tid; idx < 4096; idx += 128)
        A[(idx >> 6) * 65 + (idx & 63)] = cov[k * 4096 + idx];
    __syncthreads();

    // blocked right-looking Cholesky: 8 panels of 8 columns
    #pragma unroll 1
    for (int p = 0; p < 8; ++p) {
        const int c0 = p * 8;
        if (tid < 32) {                       // panel: warp 0, register-resident
            const int r0 = c0 + l, r1 = c0 + 32 + l;
            const bool act0 = (r0 < 64), act1 = (r1 < 64);
            float a0[8], a1[8];
            #pragma unroll
            for (int m = 0; m < 8; ++m) {
                a0[m] = act0 ? A[r0 * 65 + c0 + m] : 0.f;
                a1[m] = act1 ? A[r1 * 65 + c0 + m] : 0.f;
            }
            #pragma unroll
            for (int jj = 0; jj < 8; ++jj) {
                const float d = __shfl_sync(0xffffffffu, a0[jj], jj);
                const float rs = rsqrtf(d);
                if (act0 && l >= jj) a0[jj] *= rs;
                if (act1)            a1[jj] *= rs;
                float lv[8];
                #pragma unroll
                for (int m = jj + 1; m < 8; ++m)
                    lv[m] = __shfl_sync(0xffffffffu, a0[jj], m);
                #pragma unroll
                for (int m = jj + 1; m < 8; ++m) {
                    if (act0 && l > jj) a0[m] -= a0[jj] * lv[m];
                    if (act1)           a1[m] -= a1[jj] * lv[m];
                }
            }
            #pragma unroll
            for (int m = 0; m < 8; ++m) {
                if (act0) A[r0 * 65 + c0 + m] = a0[m];
                if (act1) A[r1 * 65 + c0 + m] = a1[m];
            }
        }
        __syncthreads();
        // trailing rank-8 update, lower triangle only; 128 threads
        const int R = 56 - c0;
        if (R > 0) {
            const int rr = tid >> 1, cq = tid & 1;
            if (rr < R) {
                const int r = c0 + 8 + rr;
                float pr[8];
                #pragma unroll
                for (int m = 0; m < 8; ++m) pr[m] = A[r * 65 + c0 + m];
                #pragma unroll 4
                for (int cc = cq; cc <= rr; cc += 2) {
                    const int c = c0 + 8 + cc;
                    float s0 = A[r * 65 + c], s1 = 0.f;
                    #pragma unroll
                    for (int m = 0; m < 4; ++m) {
                        s0 -= pr[m]     * A[c * 65 + c0 + m];
                        s1 += pr[m + 4] * A[c * 65 + c0 + m + 4];
                    }
                    A[r * 65 + c] = s0 - s1;
                }
            }
        }
        __syncthreads();
    }

    if (tid < 64) {
        const float dii = A[tid * 65 + tid];
        dl[tid] = 2.f * logf(dii);
        rd[tid] = 1.0f / dii;
    }
    __syncthreads();

    // forward substitution: 4 warps x 16 columns each
    {
        const int w = tid >> 5;
        const int r0 = l, r1 = l + 32;
        const int c0 = w * 16;
        float v0[16], v1[16];
        #pragma unroll
        for (int j = 0; j < 16; ++j) {
            v0[j] = (r0 == c0 + j) ? 1.f : 0.f;
            v1[j] = (r1 == c0 + j) ? 1.f : 0.f;
        }
        for (int m = 0; m < 64; ++m) {
            const float lr0 = (r0 > m) ? A[r0 * 65 + m] : 0.f;
            const float lr1 = (r1 > m) ? A[r1 * 65 + m] : 0.f;
            const float rdm = rd[m];
            const int   src = m & 31;
            const bool  lo  = (m < 32);
            #pragma unroll
            for (int j = 0; j < 16; ++j) {
                const float resid = lo ? v0[j] : v1[j];
                const float ym = __shfl_sync(0xffffffffu, resid, src) * rdm;
                v0[j] -= lr0 * ym;
                v1[j] -= lr1 * ym;
                if (l == src) Li[m * 65 + c0 + j] = ym;
            }
        }
    }
    __syncthreads();

    // t = Linv * c (fp32), 4-way partials
    if (tid < 64) {
        float s0 = 0.f, s1 = 0.f, s2 = 0.f, s3 = 0.f;
        int e = 0;
        for (; e + 3 <= tid; e += 4) {
            s0 += Li[tid * 65 + e]     * cen[k * 64 + e];
            s1 += Li[tid * 65 + e + 1] * cen[k * 64 + e + 1];
            s2 += Li[tid * 65 + e + 2] * cen[k * 64 + e + 2];
            s3 += Li[tid * 65 + e + 3] * cen[k * 64 + e + 3];
        }
        for (; e <= tid; ++e) s0 += Li[tid * 65 + e] * cen[k * 64 + e];
        tsm[tid] = (s0 + s1) + (s2 + s3);
    }
    __syncthreads();

    // u = Linv^T t (row k of the cross matrix, bf16), 4-way partials
    if (tid < 64) {
        const int e = tid;
        float s0 = 0.f, s1 = 0.f, s2 = 0.f, s3 = 0.f;
        int d = e;
        for (; d + 3 < 64; d += 4) {
            s0 += Li[d * 65 + e]       * tsm[d];
            s1 += Li[(d + 1) * 65 + e] * tsm[d + 1];
            s2 += Li[(d + 2) * 65 + e] * tsm[d + 2];
            s3 += Li[(d + 3) * 65 + e] * tsm[d + 3];
        }
        for (; d < 64; ++d) s0 += Li[d * 65 + e] * tsm[d];
        g_Wb[32 * 4096 + k * 64 + e] = __float2bfloat16_rn((s0 + s1) + (s2 + s3));
    }
    if (tid == 0) {
        float ld = 0.f, tau = 0.f;
        #pragma unroll 4
        for (int m = 0; m < 64; ++m) { ld += dl[m]; tau += tsm[m] * tsm[m]; }
        g_nhc[k] = -0.5f * (64.f * LOG2PI + ld + tau);
    }
    // bf16 W
    #pragma unroll 4
    for (int idx = tid; idx < 4096; idx += 128) {
        const int d = idx >> 6, e = idx & 63;
        const float v = (e <= d) ? Li[d * 65 + e] : 0.f;
        g_Wb[k * 4096 + idx] = __float2bfloat16_rn(v);
    }
}

// ---------------- single fused kernel -----------------------------------------
// grid = 32 prep blocks + B/256 GEMM blocks; block = 128 threads (4 warps)
__global__ void __launch_bounds__(128, 2) fused_kernel(const float* __restrict__ emb,
                                                       const float* __restrict__ cen,
                                                       const float* __restrict__ cov,
                                                       const float* __restrict__ pi,
                                                       const int* __restrict__ labels,
                                                       float* __restrict__ out)
{
    extern __shared__ char smem[];
    __nv_bfloat16* Xs  = (__nv_bfloat16*)(smem + OFF_XS);   // front phase only
    __nv_bfloat16* Ws  = (__nv_bfloat16*)(smem + OFF_WS);   // [8][SLOT] ring
    float* Ps  = (float*)(smem + OFF_PS);
    float* nhc = (float*)(smem + OFF_NHC);
    int*   lbl = (int*)  (smem + OFF_LBL);
    float* red = (float*)(smem + OFF_RED);
    int*   flg = (int*)  (smem + OFF_FLG);

    const int tid   = threadIdx.x;
    const int total = gridDim.x;         // nb + 32
    const int nb    = total - 32;

    // =================== prep blocks: prep only, then exit =====================
    if (blockIdx.x < 32) {
        do_prep(blockIdx.x, cov, cen, smem, tid);
        __syncthreads();
        if (tid == 0) {
            __threadfence();
            atomicAdd(&g_ready, 1);
            __threadfence();
            const int old = atomicAdd(&g_done, 1);
            flg[0] = (old == total - 1) ? 1 : 0;
        }
        __syncthreads();
        if (flg[0]) {                    // defensive: never last in practice
            __threadfence();
            float a = 0.f;
            for (int i = tid; i < nb; i += 128) a += g_part[i];
            red[tid] = a;
            __syncthreads();
            #pragma unroll
            for (int st = 64; st > 0; st >>= 1) {
                if (tid < st) red[tid] += red[tid + st];
                __syncthreads();
            }
            if (tid == 0) { out[0] = fabsf(red[0]); g_done = 0; g_ready = 0; }
        }
        return;
    }

    // =================== GEMM blocks ==========================================
    const int gbid = blockIdx.x - 32;
    const int b0   = gbid * 256;

    const int w    = tid >> 5;        // warp 0..3 -> rows w*64 .. w*64+63
    const int lane = tid & 31;
    const int g    = lane >> 2;
    const int t4   = lane & 3;
    const int base = w * 64;

    // ---- WARP-LOCAL front phase: labels, pi, emb, aF (no block barriers) ----
    lbl[base + lane]      = labels[b0 + base + lane];
    lbl[base + 32 + lane] = labels[b0 + base + 32 + lane];
    __syncwarp();

    // pi gather via cp.async (warp-local rows; group Gp)
    #pragma unroll
    for (int it = 0; it < 16; ++it) {
        const int idx = lane + it * 32;
        const int row = base + (idx >> 3), c8 = idx & 7;
        cp_async16(&Ps[row * PSW + c8 * 4],
                   pi + (size_t)lbl[row] * 32 + c8 * 4);
    }
    asm volatile("cp.async.commit_group;\n");

    // emb gather -> bf16 Xs (warp-local rows)
    {
        const int f4 = lane & 15, rh = lane >> 4;
        #pragma unroll 8
        for (int it = 0; it < 32; ++it) {
            const int row = base + rh + it * 2;
            const float4 v = *(const float4*)(emb + (size_t)lbl[row] * 64 + f4 * 4);
            __nv_bfloat162* p = (__nv_bfloat162*)&Xs[row * SW + f4 * 4];
            p[0] = __nv_bfloat162(__float2bfloat16_rn(v.x), __float2bfloat16_rn(v.y));
            p[1] = __nv_bfloat162(__float2bfloat16_rn(v.z), __float2bfloat16_rn(v.w));
        }
    }
    __syncwarp();

    // A fragments: loaded ONCE from this warp's Xs rows (64 regs)
    unsigned aF[4][4][4];
    #pragma unroll
    for (int es = 0; es < 4; ++es) {
        const int e0 = es * 16 + 2 * t4;
        #pragma unroll
        for (int rg = 0; rg < 4; ++rg) {
            const int r = base + rg * 16 + g;
            aF[es][rg][0] = *(const unsigned*)&Xs[r       * SW + e0];
            aF[es][rg][1] = *(const unsigned*)&Xs[(r + 8) * SW + e0];
            aF[es][rg][2] = *(const unsigned*)&Xs[r       * SW + e0 + 8];
            aF[es][rg][3] = *(const unsigned*)&Xs[(r + 8) * SW + e0 + 8];
        }
    }
    __syncthreads();   // all warps past Xs reads: W ring may overwrite it

    // ---- wait for all components (cheap volatile poll)
    if (tid == 0) {
        while (*(volatile int*)&g_ready < 32) { __nanosleep(100); }
    }
    __syncthreads();
    __threadfence();
    if (tid < 32) nhc[tid] = g_nhc[tid];

    auto prefetch = [&](int k) {
        const uint4* src = (const uint4*)(g_Wb + k * 4096);
        __nv_bfloat16* dst = Ws + (k & 7) * SLOT;
        #pragma unroll
        for (int it = 0; it < 4; ++it) {
            const int idx = tid + it * 128;
            cp_async16(&dst[(idx >> 3) * SW + (idx & 7) * 8], &src[idx]);
        }
    };

    // init: 3 pairs in flight (groups GA, GB, GC after Gp)
    prefetch(0); prefetch(1);
    asm volatile("cp.async.commit_group;\n");
    prefetch(2); prefetch(3);
    asm volatile("cp.async.commit_group;\n");
    prefetch(4); prefetch(5);
    asm volatile("cp.async.commit_group;\n");

    // 8 independent square-term accumulators + 4 cross accumulators
    float accs[4][2];
    #pragma unroll
    for (int rg = 0; rg < 4; ++rg) { accs[rg][0] = 0.f; accs[rg][1] = 0.f; }
    float accc[4] = {0.f, 0.f, 0.f, 0.f};

    // per-k compute (square path)
    auto mainK = [&](int k) {
        const __nv_bfloat16* Wk = Ws + (k & 7) * SLOT;
        float q0[4] = {0.f, 0.f, 0.f, 0.f};
        float q1[4] = {0.f, 0.f, 0.f, 0.f};
        #pragma unroll
        for (int j = 0; j < 8; ++j) {
            float c0[4], c1[4], c2[4], c3[4];
            #pragma unroll
            for (int rg = 0; rg < 4; ++rg) { c0[rg]=0.f; c1[rg]=0.f; c2[rg]=0.f; c3[rg]=0.f; }
            // lower-triangular W: rows d in [8j, 8j+8) need only e <= 8j+7
            const int esn = j / 2 + 1;
            #pragma unroll
            for (int es = 0; es < esn; ++es) {
                const int e0 = es * 16 + 2 * t4;
                const unsigned b0v = *(const unsigned*)&Wk[(j * 8 + g) * SW + e0];
                const unsigned b1v = *(const unsigned*)&Wk[(j * 8 + g) * SW + e0 + 8];
                #pragma unroll
                for (int rg = 0; rg < 4; ++rg)
                    MMA(c0[rg], c1[rg], c2[rg], c3[rg],
                        aF[es][rg][0], aF[es][rg][1], aF[es][rg][2], aF[es][rg][3],
                        b0v, b1v);
            }
            #pragma unroll
            for (int rg = 0; rg < 4; ++rg) {
                q0[rg] = fmaf(c0[rg], c0[rg], q0[rg]);
                q0[rg] = fmaf(c1[rg], c1[rg], q0[rg]);
                q1[rg] = fmaf(c2[rg], c2[rg], q1[rg]);
                q1[rg] = fmaf(c3[rg], c3[rg], q1[rg]);
            }
        }
        #pragma unroll
        for (int rg = 0; rg < 4; ++rg) {
            const int r = base + rg * 16 + g;
            accs[rg][0] = fmaf(Ps[r       * PSW + k], q0[rg], accs[rg][0]);
            accs[rg][1] = fmaf(Ps[(r + 8) * PSW + k], q1[rg], accs[rg][1]);
        }
    };

    // ---- pair loop: ONE barrier per 2 k's; prefetch 6 ahead
    #pragma unroll 1
    for (int kk = 0; kk < 32; kk += 2) {
        asm volatile("cp.async.wait_group 2;\n");   // groups through (kk,kk+1) landed
        __syncthreads();                            // visibility + slots (kk-2..kk-1) free
        if (kk + 6 <= 32) prefetch(kk + 6);
        if (kk + 7 <= 32) prefetch(kk + 7);
        asm volatile("cp.async.commit_group;\n");   // (empty group ok)
        mainK(kk);
        mainK(kk + 1);
    }

    // ---- final: cross terms  cross[b][k'] = x_b . u_k'  (slot 32&7 = 0)
    asm volatile("cp.async.wait_group 0;\n");
    __syncthreads();
    {
        const __nv_bfloat16* Wu = Ws;               // slot 0
        #pragma unroll
        for (int j = 0; j < 4; ++j) {               // k' = j*8 .. j*8+7
            float c0[4], c1[4], c2[4], c3[4];
            #pragma unroll
            for (int rg = 0; rg < 4; ++rg) { c0[rg]=0.f; c1[rg]=0.f; c2[rg]=0.f; c3[rg]=0.f; }
            #pragma unroll
            for (int es = 0; es < 4; ++es) {
                const int e0 = es * 16 + 2 * t4;
                const unsigned b0v = *(const unsigned*)&Wu[(j * 8 + g) * SW + e0];
                const unsigned b1v = *(const unsigned*)&Wu[(j * 8 + g) * SW + e0 + 8];
                #pragma unroll
                for (int rg = 0; rg < 4; ++rg)
                    MMA(c0[rg], c1[rg], c2[rg], c3[rg],
                        aF[es][rg][0], aF[es][rg][1], aF[es][rg][2], aF[es][rg][3],
                        b0v, b1v);
            }
            const int k0 = j * 8 + 2 * t4;
            #pragma unroll
            for (int rg = 0; rg < 4; ++rg) {
                const int r = base + rg * 16 + g;
                float cc;
                cc = fmaf(Ps[r       * PSW + k0],     c0[rg],
                     fmaf(Ps[r       * PSW + k0 + 1], c1[rg], 0.f));
                cc = fmaf(Ps[(r + 8) * PSW + k0],     c2[rg], cc);
                cc = fmaf(Ps[(r + 8) * PSW + k0 + 1], c3[rg], cc);
                accc[rg] += cc;
            }
        }
    }

    // deterministic combine of private partials
    float acc_sq = ((accs[0][0] + accs[0][1]) + (accs[1][0] + accs[1][1]))
                 + ((accs[2][0] + accs[2][1]) + (accs[3][0] + accs[3][1]));
    float acc_cr = (accc[0] + accc[1]) + (accc[2] + accc[3]);
    float acc = fmaf(-0.5f, acc_sq, acc_cr);

    // constant part: rows tid and tid+128
    {
        float c = 0.f;
        #pragma unroll
        for (int kk = 0; kk < 32; ++kk) {
            c = fmaf(Ps[tid * PSW + kk],         nhc[kk], c);
            c = fmaf(Ps[(tid + 128) * PSW + kk], nhc[kk], c);
        }
        acc += c;
    }

    // deterministic block reduction
    red[tid] = acc;
    __syncthreads();
    #pragma unroll
    for (int st = 64; st > 0; st >>= 1) {
        if (tid < st) red[tid] += red[tid + st];
        __syncthreads();
    }
    if (tid == 0) g_part[gbid] = red[0];

    // ---- last block overall: final reduce + reset
    if (tid == 0) {
        __threadfence();
        const int old = atomicAdd(&g_done, 1);
        flg[0] = (old == total - 1) ? 1 : 0;
    }
    __syncthreads();
    if (flg[0]) {
        __threadfence();
        float a = 0.f;
        for (int i = tid; i < nb; i += 128) a += g_part[i];
        red[tid] = a;
        __syncthreads();
        #pragma unroll
        for (int st = 64; st > 0; st >>= 1) {
            if (tid < st) red[tid] += red[tid + st];
            __syncthreads();
        }
        if (tid == 0) {
            out[0] = fabsf(red[0]);
            g_done  = 0;
            g_ready = 0;
        }
    }
}

// ---------------- launch ----------------
extern "C" void kernel_launch(void* const* d_in, const int* in_sizes, int n_in,
                              void* d_out, int out_size)
{
    const float* emb    = (const float*)d_in[0];   // (500000, 64)
    const float* cen    = (const float*)d_in[1];   // (32, 64)
    const float* cov    = (const float*)d_in[2];   // (32, 64, 64)
    const float* pi     = (const float*)d_in[3];   // (500000, 32)
    const int*   labels = (const int*)d_in[4];     // (B,)
    const int B  = in_sizes[4];
    const int nb = B / 256;

    static int configured = 0;
    if (!configured) {
        cudaFuncSetAttribute(fused_kernel, cudaFuncAttributeMaxDynamicSharedMemorySize,
                             SMEM_TOTAL);
        configured = 1;
    }

    fused_kernel<<<nb + 32, 128, SMEM_TOTAL>>>(emb, cen, cov, pi, labels,
                                               (float*)d_out);
}

// round 15
// speedup vs baseline: 1.0580x; 1.0432x over previous
#include <cuda_runtime.h>
#include <cuda_bf16.h>
#include <math.h>

// ---------------- device scratch (no allocations allowed) ----------------
__device__ __nv_bfloat16 g_Wb[33 * 64 * 64]; // [k][d][e]; slot 32 = U (cross)
__device__ float g_nhc[32];                  // -0.5*(D*log2pi + logdet + tau)
__device__ float g_part[4096];               // per-block partial sums
__device__ int   g_ready;                    // # components prepped
__device__ int   g_done;                     // # blocks finished

#define LOG2PI 1.8378770664093453f
#define SW 72      // bf16 smem row stride: conflict-free fragment LDS
#define PSW 36     // Ps float stride: 144B rows (16B-aligned for cp.async)
#define SLOT 4608  // bf16 elems per W slot (64*SW)

// dynamic smem layout (bytes).
// [0, 73728): W ring, 8 slots of 9216B. Front phase overlays Xs (36864B)
// here; prep blocks overlay their Cholesky workspace (~34KB) here too.
#define OFF_XS   0
#define OFF_WS   0
#define OFF_PS   73728                      // float [256*PSW]          36864
#define OFF_NHC  110592                     // float [32]                 128
#define OFF_LBL  110720                     // int   [256]               1024
#define OFF_RED  111744                     // float [256]               1024
#define OFF_FLG  112768                     // int                         16
#define SMEM_TOTAL 112784

__device__ __forceinline__ void cp_async16(void* dst, const void* src) {
    unsigned a = (unsigned)__cvta_generic_to_shared(dst);
    asm volatile("cp.async.ca.shared.global [%0], [%1], 16;\n"
                 :: "r"(a), "l"(src) : "memory");
}

#define MMA(c0,c1,c2,c3,a0,a1,a2,a3,b0,b1)                                   \
    asm volatile(                                                            \
        "mma.sync.aligned.m16n8k16.row.col.f32.bf16.bf16.f32 "               \
        "{%0,%1,%2,%3}, {%4,%5,%6,%7}, {%8,%9}, {%0,%1,%2,%3};\n"            \
        : "+f"(c0), "+f"(c1), "+f"(c2), "+f"(c3)                             \
        : "r"(a0), "r"(a1), "r"(a2), "r"(a3), "r"(b0), "r"(b1))

// ---------------- prep: PIPELINED panel Cholesky (256 threads) ----------------
// Stage s: warp 0 strip-updates panel s (w.r.t. panel s-1 only) and
// factorizes it in registers; warps 1-7 apply panel s-1 to columns >= 8(s+1).
// Invariant: entering stage s, panel-s cols hold contributions of panels 0..s-2.
__device__ void do_prep(int k, const float* __restrict__ cov,
                        const float* __restrict__ cen, char* smem_raw, int tid)
{
    float* A    = (float*)smem_raw;          // 64*65
    float* Li   = A  + 64 * 65;              // 64*65
    float* rd   = Li + 64 * 65;              // 64
    float* dl   = rd + 64;                   // 64
    float* tsm  = dl + 64;                   // 64

    const int l  = tid & 31;
    const int wp = tid >> 5;

    for (int idx = tid; idx < 4096; idx += 256)
        A[(idx >> 6) * 65 + (idx & 63)] = cov[k * 4096 + idx];
    __syncthreads();

    #pragma unroll 1
    for (int s = 0; s < 8; ++s) {
        const int c0 = s * 8;
        if (wp == 0) {
            // ---- warp 0: strip update (panel s-1 only) + factorize panel s
            const int r0 = c0 + l, r1 = c0 + 32 + l;
            const bool act0 = (r0 < 64), act1 = (r1 < 64);
            float a0[8], a1[8];
            #pragma unroll
            for (int m = 0; m < 8; ++m) {
                a0[m] = act0 ? A[r0 * 65 + c0 + m] : 0.f;
                a1[m] = act1 ? A[r1 * 65 + c0 + m] : 0.f;
            }
            if (s > 0) {
                const int q0 = c0 - 8;
                float lr0[8], lr1[8];
                #pragma unroll
                for (int i = 0; i < 8; ++i) {
                    lr0[i] = act0 ? A[r0 * 65 + q0 + i] : 0.f;
                    lr1[i] = act1 ? A[r1 * 65 + q0 + i] : 0.f;
                }
                #pragma unroll
                for (int m = 0; m < 8; ++m) {
                    float lc[8];
                    #pragma unroll
                    for (int i = 0; i < 8; ++i)
                        lc[i] = A[(c0 + m) * 65 + q0 + i];  // broadcast LDS
                    #pragma unroll
                    for (int i = 0; i < 8; ++i) {
                        a0[m] -= lr0[i] * lc[i];
                        a1[m] -= lr1[i] * lc[i];
                    }
                }
            }
            // factorize 8x8 panel in registers (shfl-based)
            #pragma unroll
            for (int jj = 0; jj < 8; ++jj) {
                const float d = __shfl_sync(0xffffffffu, a0[jj], jj);
                const float rs = rsqrtf(d);
                if (act0 && l >= jj) a0[jj] *= rs;
                if (act1)            a1[jj] *= rs;
                float lv[8];
                #pragma unroll
                for (int m = jj + 1; m < 8; ++m)
                    lv[m] = __shfl_sync(0xffffffffu, a0[jj], m);
                #pragma unroll
                for (int m = jj + 1; m < 8; ++m) {
                    if (act0 && l > jj) a0[m] -= a0[jj] * lv[m];
                    if (act1)           a1[m] -= a1[jj] * lv[m];
                }
            }
            #pragma unroll
            for (int m = 0; m < 8; ++m) {
                if (act0) A[r0 * 65 + c0 + m] = a0[m];
                if (act1) A[r1 * 65 + c0 + m] = a1[m];
            }
        } else if (s > 0) {
            // ---- helpers: apply panel s-1 to cols >= 8(s+1), rows >= col
            const int cbase = c0 + 8;
            if (cbase < 64) {
                const int q0 = c0 - 8;
                const int ht = tid - 32;            // 0..223
                const int r  = cbase + (ht >> 2);
                const int cq = ht & 3;
                if (r < 64) {
                    float pr[8];
                    #pragma unroll
                    for (int i = 0; i < 8; ++i) pr[i] = A[r * 65 + q0 + i];
                    for (int c = cbase + cq; c <= r; c += 4) {
                        float v = A[r * 65 + c];
                        #pragma unroll
                        for (int i = 0; i < 8; ++i)
                            v -= pr[i] * A[c * 65 + q0 + i];
                        A[r * 65 + c] = v;
                    }
                }
            }
        }
        __syncthreads();
    }

    if (tid < 64) {
        const float dii = A[tid * 65 + tid];
        dl[tid] = 2.f * logf(dii);
        rd[tid] = 1.0f / dii;
    }
    __syncthreads();

    // forward substitution: 8 warps x 8 columns each
    {
        const int r0 = l, r1 = l + 32;
        const int c0 = wp * 8;
        float v0[8], v1[8];
        #pragma unroll
        for (int j = 0; j < 8; ++j) {
            v0[j] = (r0 == c0 + j) ? 1.f : 0.f;
            v1[j] = (r1 == c0 + j) ? 1.f : 0.f;
        }
        for (int m = 0; m < 64; ++m) {
            const float lr0 = (r0 > m) ? A[r0 * 65 + m] : 0.f;
            const float lr1 = (r1 > m) ? A[r1 * 65 + m] : 0.f;
            const float rdm = rd[m];
            const int   src = m & 31;
            const bool  lo  = (m < 32);
            #pragma unroll
            for (int j = 0; j < 8; ++j) {
                const float resid = lo ? v0[j] : v1[j];
                const float ym = __shfl_sync(0xffffffffu, resid, src) * rdm;
                v0[j] -= lr0 * ym;
                v1[j] -= lr1 * ym;
                if (l == src) Li[m * 65 + c0 + j] = ym;
            }
        }
    }
    __syncthreads();

    // t = Linv * c (fp32), 4-way partials
    if (tid < 64) {
        float s0 = 0.f, s1 = 0.f, s2 = 0.f, s3 = 0.f;
        int e = 0;
        for (; e + 3 <= tid; e += 4) {
            s0 += Li[tid * 65 + e]     * cen[k * 64 + e];
            s1 += Li[tid * 65 + e + 1] * cen[k * 64 + e + 1];
            s2 += Li[tid * 65 + e + 2] * cen[k * 64 + e + 2];
            s3 += Li[tid * 65 + e + 3] * cen[k * 64 + e + 3];
        }
        for (; e <= tid; ++e) s0 += Li[tid * 65 + e] * cen[k * 64 + e];
        tsm[tid] = (s0 + s1) + (s2 + s3);
    }
    __syncthreads();

    // u = Linv^T t (bf16 row k of cross matrix), 4-way partials
    if (tid < 64) {
        const int e = tid;
        float s0 = 0.f, s1 = 0.f, s2 = 0.f, s3 = 0.f;
        int d = e;
        for (; d + 3 < 64; d += 4) {
            s0 += Li[d * 65 + e]       * tsm[d];
            s1 += Li[(d + 1) * 65 + e] * tsm[d + 1];
            s2 += Li[(d + 2) * 65 + e] * tsm[d + 2];
            s3 += Li[(d + 3) * 65 + e] * tsm[d + 3];
        }
        for (; d < 64; ++d) s0 += Li[d * 65 + e] * tsm[d];
        g_Wb[32 * 4096 + k * 64 + e] = __float2bfloat16_rn((s0 + s1) + (s2 + s3));
    }
    if (tid == 0) {
        float ld = 0.f, tau = 0.f;
        #pragma unroll 4
        for (int m = 0; m < 64; ++m) { ld += dl[m]; tau += tsm[m] * tsm[m]; }
        g_nhc[k] = -0.5f * (64.f * LOG2PI + ld + tau);
    }
    #pragma unroll 4
    for (int idx = tid; idx < 4096; idx += 256) {
        const int d = idx >> 6, e = idx & 63;
        const float v = (e <= d) ? Li[d * 65 + e] : 0.f;
        g_Wb[k * 4096 + idx] = __float2bfloat16_rn(v);
    }
}

// ---------------- single fused kernel -----------------------------------------
// grid = 32 prep blocks + B/256 GEMM blocks; block = 256 threads (8 warps)
__global__ void __launch_bounds__(256, 2) fused_kernel(const float* __restrict__ emb,
                                                       const float* __restrict__ cen,
                                                       const float* __restrict__ cov,
                                                       const float* __restrict__ pi,
                                                       const int* __restrict__ labels,
                                                       float* __restrict__ out)
{
    extern __shared__ char smem[];
    __nv_bfloat16* Xs  = (__nv_bfloat16*)(smem + OFF_XS);   // front phase only
    __nv_bfloat16* Ws  = (__nv_bfloat16*)(smem + OFF_WS);   // [8][SLOT] ring
    float* Ps  = (float*)(smem + OFF_PS);
    float* nhc = (float*)(smem + OFF_NHC);
    int*   lbl = (int*)  (smem + OFF_LBL);
    float* red = (float*)(smem + OFF_RED);
    int*   flg = (int*)  (smem + OFF_FLG);

    const int tid   = threadIdx.x;
    const int total = gridDim.x;         // nb + 32
    const int nb    = total - 32;

    // =================== prep blocks: prep only, then exit =====================
    if (blockIdx.x < 32) {
        do_prep(blockIdx.x, cov, cen, smem, tid);
        __syncthreads();
        if (tid == 0) {
            __threadfence();
            atomicAdd(&g_ready, 1);
            __threadfence();
            const int old = atomicAdd(&g_done, 1);
            flg[0] = (old == total - 1) ? 1 : 0;
        }
        __syncthreads();
        if (flg[0]) {                    // defensive: never last in practice
            __threadfence();
            float a = 0.f;
            for (int i = tid; i < nb; i += 256) a += g_part[i];
            red[tid] = a;
            __syncthreads();
            #pragma unroll
            for (int st = 128; st > 0; st >>= 1) {
                if (tid < st) red[tid] += red[tid + st];
                __syncthreads();
            }
            if (tid == 0) { out[0] = fabsf(red[0]); g_done = 0; g_ready = 0; }
        }
        return;
    }

    // =================== GEMM blocks ==========================================
    const int gbid = blockIdx.x - 32;
    const int b0   = gbid * 256;

    const int w    = tid >> 5;        // warp 0..7 -> rows w*32 .. w*32+31
    const int lane = tid & 31;
    const int g    = lane >> 2;
    const int t4   = lane & 3;
    const int base = w * 32;

    // ---- WARP-LOCAL front phase (no block barriers) ----
    lbl[base + lane] = labels[b0 + base + lane];
    __syncwarp();

    // pi gather via cp.async (warp-local rows; 8 chunks/lane)
    #pragma unroll
    for (int it = 0; it < 8; ++it) {
        const int idx = lane + it * 32;
        const int row = base + (idx >> 3), c8 = idx & 7;
        cp_async16(&Ps[row * PSW + c8 * 4],
                   pi + (size_t)lbl[row] * 32 + c8 * 4);
    }
    asm volatile("cp.async.commit_group;\n");

    // emb gather -> bf16 Xs (warp-local rows)
    {
        const int f4 = lane & 15, rh = lane >> 4;
        #pragma unroll 8
        for (int it = 0; it < 16; ++it) {
            const int row = base + rh + it * 2;
            const float4 v = *(const float4*)(emb + (size_t)lbl[row] * 64 + f4 * 4);
            __nv_bfloat162* p = (__nv_bfloat162*)&Xs[row * SW + f4 * 4];
            p[0] = __nv_bfloat162(__float2bfloat16_rn(v.x), __float2bfloat16_rn(v.y));
            p[1] = __nv_bfloat162(__float2bfloat16_rn(v.z), __float2bfloat16_rn(v.w));
        }
    }
    __syncwarp();

    // A fragments: loaded ONCE from this warp's Xs rows (32 regs)
    unsigned aF[4][2][4];
    #pragma unroll
    for (int es = 0; es < 4; ++es) {
        const int e0 = es * 16 + 2 * t4;
        #pragma unroll
        for (int rg = 0; rg < 2; ++rg) {
            const int r = base + rg * 16 + g;
            aF[es][rg][0] = *(const unsigned*)&Xs[r       * SW + e0];
            aF[es][rg][1] = *(const unsigned*)&Xs[(r + 8) * SW + e0];
            aF[es][rg][2] = *(const unsigned*)&Xs[r       * SW + e0 + 8];
            aF[es][rg][3] = *(const unsigned*)&Xs[(r + 8) * SW + e0 + 8];
        }
    }
    __syncthreads();   // all warps past Xs reads: W ring may overwrite it

    // ---- wait for all components (cheap volatile poll)
    if (tid == 0) {
        while (*(volatile int*)&g_ready < 32) { __nanosleep(100); }
    }
    __syncthreads();
    __threadfence();
    if (tid < 32) nhc[tid] = g_nhc[tid];

    auto prefetch = [&](int k) {
        const uint4* src = (const uint4*)(g_Wb + k * 4096);
        __nv_bfloat16* dst = Ws + (k & 7) * SLOT;
        #pragma unroll
        for (int it = 0; it < 2; ++it) {
            const int idx = tid + it * 256;
            cp_async16(&dst[(idx >> 3) * SW + (idx & 7) * 8], &src[idx]);
        }
    };

    // init: 3 pairs in flight
    prefetch(0); prefetch(1);
    asm volatile("cp.async.commit_group;\n");
    prefetch(2); prefetch(3);
    asm volatile("cp.async.commit_group;\n");
    prefetch(4); prefetch(5);
    asm volatile("cp.async.commit_group;\n");

    // 4 independent square-term accumulators + 2 cross accumulators
    float accs[2][2];
    #pragma unroll
    for (int rg = 0; rg < 2; ++rg) { accs[rg][0] = 0.f; accs[rg][1] = 0.f; }
    float accc[2] = {0.f, 0.f};

    // per-k compute (square path)
    auto mainK = [&](int k) {
        const __nv_bfloat16* Wk = Ws + (k & 7) * SLOT;
        float q0[2] = {0.f, 0.f};
        float q1[2] = {0.f, 0.f};
        #pragma unroll
        for (int j = 0; j < 8; ++j) {
            float c0[2], c1[2], c2[2], c3[2];
            #pragma unroll
            for (int rg = 0; rg < 2; ++rg) { c0[rg]=0.f; c1[rg]=0.f; c2[rg]=0.f; c3[rg]=0.f; }
            // lower-triangular W: rows d in [8j, 8j+8) need only e <= 8j+7
            const int esn = j / 2 + 1;
            #pragma unroll
            for (int es = 0; es < esn; ++es) {
                const int e0 = es * 16 + 2 * t4;
                const unsigned b0v = *(const unsigned*)&Wk[(j * 8 + g) * SW + e0];
                const unsigned b1v = *(const unsigned*)&Wk[(j * 8 + g) * SW + e0 + 8];
                #pragma unroll
                for (int rg = 0; rg < 2; ++rg)
                    MMA(c0[rg], c1[rg], c2[rg], c3[rg],
                        aF[es][rg][0], aF[es][rg][1], aF[es][rg][2], aF[es][rg][3],
                        b0v, b1v);
            }
            #pragma unroll
            for (int rg = 0; rg < 2; ++rg) {
                q0[rg] = fmaf(c0[rg], c0[rg], q0[rg]);
                q0[rg] = fmaf(c1[rg], c1[rg], q0[rg]);
                q1[rg] = fmaf(c2[rg], c2[rg], q1[rg]);
                q1[rg] = fmaf(c3[rg], c3[rg], q1[rg]);
            }
        }
        #pragma unroll
        for (int rg = 0; rg < 2; ++rg) {
            const int r = base + rg * 16 + g;
            accs[rg][0] = fmaf(Ps[r       * PSW + k], q0[rg], accs[rg][0]);
            accs[rg][1] = fmaf(Ps[(r + 8) * PSW + k], q1[rg], accs[rg][1]);
        }
    };

    // ---- pair loop: ONE barrier per 2 k's; prefetch 6 ahead
    #pragma unroll 1
    for (int kk = 0; kk < 32; kk += 2) {
        asm volatile("cp.async.wait_group 2;\n");   // groups through (kk,kk+1) landed
        __syncthreads();                            // visibility + slots free
        if (kk + 6 <= 32) prefetch(kk + 6);
        if (kk + 7 <= 32) prefetch(kk + 7);
        asm volatile("cp.async.commit_group;\n");
        mainK(kk);
        mainK(kk + 1);
    }

    // ---- final: cross terms  cross[b][k'] = x_b . u_k'  (slot 32&7 = 0)
    asm volatile("cp.async.wait_group 0;\n");
    __syncthreads();
    {
        const __nv_bfloat16* Wu = Ws;               // slot 0
        #pragma unroll
        for (int j = 0; j < 4; ++j) {               // k' = j*8 .. j*8+7
            float c0[2], c1[2], c2[2], c3[2];
            #pragma unroll
            for (int rg = 0; rg < 2; ++rg) { c0[rg]=0.f; c1[rg]=0.f; c2[rg]=0.f; c3[rg]=0.f; }
            #pragma unroll
            for (int es = 0; es < 4; ++es) {
                const int e0 = es * 16 + 2 * t4;
                const unsigned b0v = *(const unsigned*)&Wu[(j * 8 + g) * SW + e0];
                const unsigned b1v = *(const unsigned*)&Wu[(j * 8 + g) * SW + e0 + 8];
                #pragma unroll
                for (int rg = 0; rg < 2; ++rg)
                    MMA(c0[rg], c1[rg], c2[rg], c3[rg],
                        aF[es][rg][0], aF[es][rg][1], aF[es][rg][2], aF[es][rg][3],
                        b0v, b1v);
            }
            const int k0 = j * 8 + 2 * t4;
            #pragma unroll
            for (int rg = 0; rg < 2; ++rg) {
                const int r = base + rg * 16 + g;
                float cc;
                cc = fmaf(Ps[r       * PSW + k0],     c0[rg],
                     fmaf(Ps[r       * PSW + k0 + 1], c1[rg], 0.f));
                cc = fmaf(Ps[(r + 8) * PSW + k0],     c2[rg], cc);
                cc = fmaf(Ps[(r + 8) * PSW + k0 + 1], c3[rg], cc);
                accc[rg] += cc;
            }
        }
    }

    // deterministic combine of private partials
    float acc_sq = (accs[0][0] + accs[0][1]) + (accs[1][0] + accs[1][1]);
    float acc_cr = accc[0] + accc[1];
    float acc = fmaf(-0.5f, acc_sq, acc_cr);

    // constant part: row tid
    {
        float c = 0.f;
        #pragma unroll
        for (int kk = 0; kk < 32; ++kk)
            c = fmaf(Ps[tid * PSW + kk], nhc[kk], c);
        acc += c;
    }

    // deterministic block reduction
    red[tid] = acc;
    __syncthreads();
    #pragma unroll
    for (int st = 128; st > 0; st >>= 1) {
        if (tid < st) red[tid] += red[tid + st];
        __syncthreads();
    }
    if (tid == 0) g_part[gbid] = red[0];

    // ---- last block overall: final reduce + reset
    if (tid == 0) {
        __threadfence();
        const int old = atomicAdd(&g_done, 1);
        flg[0] = (old == total - 1) ? 1 : 0;
    }
    __syncthreads();
    if (flg[0]) {
        __threadfence();
        float a = 0.f;
        for (int i = tid; i < nb; i += 256) a += g_part[i];
        red[tid] = a;
        __syncthreads();
        #pragma unroll
        for (int st = 128; st > 0; st >>= 1) {
            if (tid < st) red[tid] += red[tid + st];
            __syncthreads();
        }
        if (tid == 0) {
            out[0] = fabsf(red[0]);
            g_done  = 0;
            g_ready = 0;
        }
    }
}

// ---------------- launch ----------------
extern "C" void kernel_launch(void* const* d_in, const int* in_sizes, int n_in,
                              void* d_out, int out_size)
{
    const float* emb    = (const float*)d_in[0];   // (500000, 64)
    const float* cen    = (const float*)d_in[1];   // (32, 64)
    const float* cov    = (const float*)d_in[2];   // (32, 64, 64)
    const float* pi     = (const float*)d_in[3];   // (500000, 32)
    const int*   labels = (const int*)d_in[4];     // (B,)
    const int B  = in_sizes[4];
    const int nb = B / 256;

    static int configured = 0;
    if (!configured) {
        cudaFuncSetAttribute(fused_kernel, cudaFuncAttributeMaxDynamicSharedMemorySize,
                             SMEM_TOTAL);
        configured = 1;
    }

    fused_kernel<<<nb + 32, 256, SMEM_TOTAL>>>(emb, cen, cov, pi, labels,
                                               (float*)d_out);
}

// round 16
// speedup vs baseline: 1.0676x; 1.0090x over previous
#include <cuda_runtime.h>
#include <cuda_bf16.h>
#include <math.h>

// ---------------- device scratch (no allocations allowed) ----------------
// g_Wb rows are PERMUTED within each 16-element block:
//   new position 16*blk + 4*t4 + 2*h + b  <-  old element 16*blk + 2*t4 + b + 8*h
// so thread (g,t4)'s two MMA B-operand words are one contiguous 8B load.
__device__ __nv_bfloat16 g_Wb[33 * 64 * 64]; // [k][d][pe]; slot 32 = U (cross)
__device__ float g_nhc[32];                  // -0.5*(D*log2pi + logdet + tau)
__device__ float g_part[4096];               // per-block partial sums
__device__ int   g_ready;                    // # components prepped
__device__ int   g_done;                     // # blocks finished

#define LOG2PI 1.8378770664093453f
#define SW  72     // Xs bf16 stride (front phase; conflict-free aF LDS.32)
#define SWW 80     // W slot bf16 row stride (160B: conflict-free LDS.64)
#define PSW 36     // Ps float stride (144B, 16B-aligned for cp.async)
#define SLOT_E (64 * SWW)   // 5120 bf16 = 10240 B per W slot
#define NSLOT 6

// dynamic smem layout (bytes).
// [0, 61440): W ring, 6 slots of 10240B. Front phase overlays Xs (36864B)
// here; prep blocks overlay their Cholesky workspace (~34KB) here too.
#define OFF_XS   0
#define OFF_WS   0
#define OFF_PS   61440                      // float [256*PSW]          36864
#define OFF_NHC  98304                      // float [32]                 128
#define OFF_LBL  98432                      // int   [256]               1024
#define OFF_RED  99456                      // float [256]               1024
#define OFF_FLG  100480                     // int                         16
#define SMEM_TOTAL 100496

__device__ __forceinline__ void cp_async16(void* dst, const void* src) {
    unsigned a = (unsigned)__cvta_generic_to_shared(dst);
    asm volatile("cp.async.ca.shared.global [%0], [%1], 16;\n"
                 :: "r"(a), "l"(src) : "memory");
}

#define MMA(c0,c1,c2,c3,a0,a1,a2,a3,b0,b1)                                   \
    asm volatile(                                                            \
        "mma.sync.aligned.m16n8k16.row.col.f32.bf16.bf16.f32 "               \
        "{%0,%1,%2,%3}, {%4,%5,%6,%7}, {%8,%9}, {%0,%1,%2,%3};\n"            \
        : "+f"(c0), "+f"(c1), "+f"(c2), "+f"(c3)                             \
        : "r"(a0), "r"(a1), "r"(a2), "r"(a3), "r"(b0), "r"(b1))

// ---------------- prep: PIPELINED panel Cholesky (256 threads) ----------------
__device__ void do_prep(int k, const float* __restrict__ cov,
                        const float* __restrict__ cen, char* smem_raw, int tid)
{
    float* A    = (float*)smem_raw;          // 64*65
    float* Li   = A  + 64 * 65;              // 64*65
    float* rd   = Li + 64 * 65;              // 64
    float* dl   = rd + 64;                   // 64
    float* tsm  = dl + 64;                   // 64

    const int l  = tid & 31;
    const int wp = tid >> 5;

    for (int idx = tid; idx < 4096; idx += 256)
        A[(idx >> 6) * 65 + (idx & 63)] = cov[k * 4096 + idx];
    __syncthreads();

    #pragma unroll 1
    for (int s = 0; s < 8; ++s) {
        const int c0 = s * 8;
        if (wp == 0) {
            // ---- warp 0: strip update (panel s-1 only) + factorize panel s
            const int r0 = c0 + l, r1 = c0 + 32 + l;
            const bool act0 = (r0 < 64), act1 = (r1 < 64);
            float a0[8], a1[8];
            #pragma unroll
            for (int m = 0; m < 8; ++m) {
                a0[m] = act0 ? A[r0 * 65 + c0 + m] : 0.f;
                a1[m] = act1 ? A[r1 * 65 + c0 + m] : 0.f;
            }
            if (s > 0) {
                const int q0 = c0 - 8;
                float lr0[8], lr1[8];
                #pragma unroll
                for (int i = 0; i < 8; ++i) {
                    lr0[i] = act0 ? A[r0 * 65 + q0 + i] : 0.f;
                    lr1[i] = act1 ? A[r1 * 65 + q0 + i] : 0.f;
                }
                #pragma unroll
                for (int m = 0; m < 8; ++m) {
                    float lc[8];
                    #pragma unroll
                    for (int i = 0; i < 8; ++i)
                        lc[i] = A[(c0 + m) * 65 + q0 + i];  // broadcast LDS
                    #pragma unroll
                    for (int i = 0; i < 8; ++i) {
                        a0[m] -= lr0[i] * lc[i];
                        a1[m] -= lr1[i] * lc[i];
                    }
                }
            }
            #pragma unroll
            for (int jj = 0; jj < 8; ++jj) {
                const float d = __shfl_sync(0xffffffffu, a0[jj], jj);
                const float rs = rsqrtf(d);
                if (act0 && l >= jj) a0[jj] *= rs;
                if (act1)            a1[jj] *= rs;
                float lv[8];
                #pragma unroll
                for (int m = jj + 1; m < 8; ++m)
                    lv[m] = __shfl_sync(0xffffffffu, a0[jj], m);
                #pragma unroll
                for (int m = jj + 1; m < 8; ++m) {
                    if (act0 && l > jj) a0[m] -= a0[jj] * lv[m];
                    if (act1)           a1[m] -= a1[jj] * lv[m];
                }
            }
            #pragma unroll
            for (int m = 0; m < 8; ++m) {
                if (act0) A[r0 * 65 + c0 + m] = a0[m];
                if (act1) A[r1 * 65 + c0 + m] = a1[m];
            }
        } else if (s > 0) {
            // ---- helpers: apply panel s-1 to cols >= 8(s+1), rows >= col
            const int cbase = c0 + 8;
            if (cbase < 64) {
                const int q0 = c0 - 8;
                const int ht = tid - 32;            // 0..223
                const int r  = cbase + (ht >> 2);
                const int cq = ht & 3;
                if (r < 64) {
                    float pr[8];
                    #pragma unroll
                    for (int i = 0; i < 8; ++i) pr[i] = A[r * 65 + q0 + i];
                    for (int c = cbase + cq; c <= r; c += 4) {
                        float v = A[r * 65 + c];
                        #pragma unroll
                        for (int i = 0; i < 8; ++i)
                            v -= pr[i] * A[c * 65 + q0 + i];
                        A[r * 65 + c] = v;
                    }
                }
            }
        }
        __syncthreads();
    }

    if (tid < 64) {
        const float dii = A[tid * 65 + tid];
        dl[tid] = 2.f * logf(dii);
        rd[tid] = 1.0f / dii;
    }
    __syncthreads();

    // forward substitution: 8 warps x 8 columns each
    {
        const int r0 = l, r1 = l + 32;
        const int c0 = wp * 8;
        float v0[8], v1[8];
        #pragma unroll
        for (int j = 0; j < 8; ++j) {
            v0[j] = (r0 == c0 + j) ? 1.f : 0.f;
            v1[j] = (r1 == c0 + j) ? 1.f : 0.f;
        }
        for (int m = 0; m < 64; ++m) {
            const float lr0 = (r0 > m) ? A[r0 * 65 + m] : 0.f;
            const float lr1 = (r1 > m) ? A[r1 * 65 + m] : 0.f;
            const float rdm = rd[m];
            const int   src = m & 31;
            const bool  lo  = (m < 32);
            #pragma unroll
            for (int j = 0; j < 8; ++j) {
                const float resid = lo ? v0[j] : v1[j];
                const float ym = __shfl_sync(0xffffffffu, resid, src) * rdm;
                v0[j] -= lr0 * ym;
                v1[j] -= lr1 * ym;
                if (l == src) Li[m * 65 + c0 + j] = ym;
            }
        }
    }
    __syncthreads();

    // t = Linv * c (fp32), 4-way partials
    if (tid < 64) {
        float s0 = 0.f, s1 = 0.f, s2 = 0.f, s3 = 0.f;
        int e = 0;
        for (; e + 3 <= tid; e += 4) {
            s0 += Li[tid * 65 + e]     * cen[k * 64 + e];
            s1 += Li[tid * 65 + e + 1] * cen[k * 64 + e + 1];
            s2 += Li[tid * 65 + e + 2] * cen[k * 64 + e + 2];
            s3 += Li[tid * 65 + e + 3] * cen[k * 64 + e + 3];
        }
        for (; e <= tid; ++e) s0 += Li[tid * 65 + e] * cen[k * 64 + e];
        tsm[tid] = (s0 + s1) + (s2 + s3);
    }
    __syncthreads();

    // u = Linv^T t (bf16 row k of cross matrix), PERMUTED column position
    if (tid < 64) {
        const int e = tid;
        float s0 = 0.f, s1 = 0.f, s2 = 0.f, s3 = 0.f;
        int d = e;
        for (; d + 3 < 64; d += 4) {
            s0 += Li[d * 65 + e]       * tsm[d];
            s1 += Li[(d + 1) * 65 + e] * tsm[d + 1];
            s2 += Li[(d + 2) * 65 + e] * tsm[d + 2];
            s3 += Li[(d + 3) * 65 + e] * tsm[d + 3];
        }
        for (; d < 64; ++d) s0 += Li[d * 65 + e] * tsm[d];
        const int le = e & 15;
        const int t4 = (le & 7) >> 1, b = le & 1, h = le >> 3;
        const int pe = (e & ~15) + 4 * t4 + 2 * h + b;
        g_Wb[32 * 4096 + k * 64 + pe] = __float2bfloat16_rn((s0 + s1) + (s2 + s3));
    }
    if (tid == 0) {
        float ld = 0.f, tau = 0.f;
        #pragma unroll 4
        for (int m = 0; m < 64; ++m) { ld += dl[m]; tau += tsm[m] * tsm[m]; }
        g_nhc[k] = -0.5f * (64.f * LOG2PI + ld + tau);
    }
    // bf16 W, permuted within each 16-element block
    #pragma unroll 4
    for (int idx = tid; idx < 4096; idx += 256) {
        const int d = idx >> 6, pe = idx & 63;
        const int lp = pe & 15;
        const int t4 = lp >> 2, r = lp & 3;
        const int oe = (pe & ~15) + 2 * t4 + (r & 1) + (r >> 1) * 8;
        const float v = (oe <= d) ? Li[d * 65 + oe] : 0.f;
        g_Wb[k * 4096 + idx] = __float2bfloat16_rn(v);
    }
}

// ---------------- single fused kernel -----------------------------------------
// grid = 32 prep blocks + B/256 GEMM blocks; block = 256 threads (8 warps)
__global__ void __launch_bounds__(256, 2) fused_kernel(const float* __restrict__ emb,
                                                       const float* __restrict__ cen,
                                                       const float* __restrict__ cov,
                                                       const float* __restrict__ pi,
                                                       const int* __restrict__ labels,
                                                       float* __restrict__ out)
{
    extern __shared__ char smem[];
    __nv_bfloat16* Xs  = (__nv_bfloat16*)(smem + OFF_XS);   // front phase only
    __nv_bfloat16* Ws  = (__nv_bfloat16*)(smem + OFF_WS);   // [6][SLOT_E] ring
    float* Ps  = (float*)(smem + OFF_PS);
    float* nhc = (float*)(smem + OFF_NHC);
    int*   lbl = (int*)  (smem + OFF_LBL);
    float* red = (float*)(smem + OFF_RED);
    int*   flg = (int*)  (smem + OFF_FLG);

    const int tid   = threadIdx.x;
    const int total = gridDim.x;         // nb + 32
    const int nb    = total - 32;

    // =================== prep blocks: prep only, then exit =====================
    if (blockIdx.x < 32) {
        do_prep(blockIdx.x, cov, cen, smem, tid);
        __syncthreads();
        if (tid == 0) {
            __threadfence();
            atomicAdd(&g_ready, 1);
            __threadfence();
            const int old = atomicAdd(&g_done, 1);
            flg[0] = (old == total - 1) ? 1 : 0;
        }
        __syncthreads();
        if (flg[0]) {                    // defensive: never last in practice
            __threadfence();
            float a = 0.f;
            for (int i = tid; i < nb; i += 256) a += g_part[i];
            red[tid] = a;
            __syncthreads();
            #pragma unroll
            for (int st = 128; st > 0; st >>= 1) {
                if (tid < st) red[tid] += red[tid + st];
                __syncthreads();
            }
            if (tid == 0) { out[0] = fabsf(red[0]); g_done = 0; g_ready = 0; }
        }
        return;
    }

    // =================== GEMM blocks ==========================================
    const int gbid = blockIdx.x - 32;
    const int b0   = gbid * 256;

    const int w    = tid >> 5;        // warp 0..7 -> rows w*32 .. w*32+31
    const int lane = tid & 31;
    const int g    = lane >> 2;
    const int t4   = lane & 3;
    const int base = w * 32;

    // ---- WARP-LOCAL front phase (no block barriers) ----
    lbl[base + lane] = labels[b0 + base + lane];
    __syncwarp();

    // pi gather via cp.async (warp-local rows)
    #pragma unroll
    for (int it = 0; it < 8; ++it) {
        const int idx = lane + it * 32;
        const int row = base + (idx >> 3), c8 = idx & 7;
        cp_async16(&Ps[row * PSW + c8 * 4],
                   pi + (size_t)lbl[row] * 32 + c8 * 4);
    }
    asm volatile("cp.async.commit_group;\n");

    // emb gather -> bf16 Xs (warp-local rows)
    {
        const int f4 = lane & 15, rh = lane >> 4;
        #pragma unroll 8
        for (int it = 0; it < 16; ++it) {
            const int row = base + rh + it * 2;
            const float4 v = *(const float4*)(emb + (size_t)lbl[row] * 64 + f4 * 4);
            __nv_bfloat162* p = (__nv_bfloat162*)&Xs[row * SW + f4 * 4];
            p[0] = __nv_bfloat162(__float2bfloat16_rn(v.x), __float2bfloat16_rn(v.y));
            p[1] = __nv_bfloat162(__float2bfloat16_rn(v.z), __float2bfloat16_rn(v.w));
        }
    }
    __syncwarp();

    // A fragments: loaded ONCE from this warp's Xs rows (32 regs)
    unsigned aF[4][2][4];
    #pragma unroll
    for (int es = 0; es < 4; ++es) {
        const int e0 = es * 16 + 2 * t4;
        #pragma unroll
        for (int rg = 0; rg < 2; ++rg) {
            const int r = base + rg * 16 + g;
            aF[es][rg][0] = *(const unsigned*)&Xs[r       * SW + e0];
            aF[es][rg][1] = *(const unsigned*)&Xs[(r + 8) * SW + e0];
            aF[es][rg][2] = *(const unsigned*)&Xs[r       * SW + e0 + 8];
            aF[es][rg][3] = *(const unsigned*)&Xs[(r + 8) * SW + e0 + 8];
        }
    }
    __syncthreads();   // all warps past Xs reads: W ring may overwrite it

    // ---- wait for all components (cheap volatile poll)
    if (tid == 0) {
        while (*(volatile int*)&g_ready < 32) { __nanosleep(100); }
    }
    __syncthreads();
    __threadfence();
    if (tid < 32) nhc[tid] = g_nhc[tid];

    auto prefetch = [&](int k) {
        if (k > 32) return;
        const uint4* src = (const uint4*)(g_Wb + k * 4096);
        __nv_bfloat16* dst = Ws + (k % NSLOT) * SLOT_E;
        #pragma unroll
        for (int it = 0; it < 2; ++it) {
            const int idx = tid + it * 256;
            cp_async16(&dst[(idx >> 3) * SWW + (idx & 7) * 8], &src[idx]);
        }
    };

    // init: 2 pairs in flight
    prefetch(0); prefetch(1);
    asm volatile("cp.async.commit_group;\n");
    prefetch(2); prefetch(3);
    asm volatile("cp.async.commit_group;\n");

    // 4 independent square-term accumulators + 2 cross accumulators
    float accs[2][2];
    #pragma unroll
    for (int rg = 0; rg < 2; ++rg) { accs[rg][0] = 0.f; accs[rg][1] = 0.f; }
    float accc[2] = {0.f, 0.f};

    // per-k compute (square path); B fragments via single LDS.64 (permuted W)
    auto mainK = [&](int k) {
        const __nv_bfloat16* Wk = Ws + (k % NSLOT) * SLOT_E;
        float q0[2] = {0.f, 0.f};
        float q1[2] = {0.f, 0.f};
        #pragma unroll
        for (int j = 0; j < 8; ++j) {
            float c0[2], c1[2], c2[2], c3[2];
            #pragma unroll
            for (int rg = 0; rg < 2; ++rg) { c0[rg]=0.f; c1[rg]=0.f; c2[rg]=0.f; c3[rg]=0.f; }
            // lower-triangular W: rows d in [8j, 8j+8) need only e <= 8j+7
            const int esn = j / 2 + 1;
            #pragma unroll
            for (int es = 0; es < esn; ++es) {
                const uint2 bb = *(const uint2*)&Wk[(j * 8 + g) * SWW + es * 16 + 4 * t4];
                #pragma unroll
                for (int rg = 0; rg < 2; ++rg)
                    MMA(c0[rg], c1[rg], c2[rg], c3[rg],
                        aF[es][rg][0], aF[es][rg][1], aF[es][rg][2], aF[es][rg][3],
                        bb.x, bb.y);
            }
            #pragma unroll
            for (int rg = 0; rg < 2; ++rg) {
                q0[rg] = fmaf(c0[rg], c0[rg], q0[rg]);
                q0[rg] = fmaf(c1[rg], c1[rg], q0[rg]);
                q1[rg] = fmaf(c2[rg], c2[rg], q1[rg]);
                q1[rg] = fmaf(c3[rg], c3[rg], q1[rg]);
            }
        }
        #pragma unroll
        for (int rg = 0; rg < 2; ++rg) {
            const int r = base + rg * 16 + g;
            accs[rg][0] = fmaf(Ps[r       * PSW + k], q0[rg], accs[rg][0]);
            accs[rg][1] = fmaf(Ps[(r + 8) * PSW + k], q1[rg], accs[rg][1]);
        }
    };

    // ---- pair loop: ONE barrier per 2 k's; prefetch 2 pairs ahead
    #pragma unroll 1
    for (int kk = 0; kk < 32; kk += 2) {
        asm volatile("cp.async.wait_group 1;\n");   // group for pair kk landed
        __syncthreads();                            // visibility + pair kk-1 slots free
        prefetch(kk + 4);
        prefetch(kk + 5);
        asm volatile("cp.async.commit_group;\n");   // (empty group ok)
        mainK(kk);
        mainK(kk + 1);
    }

    // ---- final: cross terms  cross[b][k'] = x_b . u_k'  (slot 32%6 = 2)
    asm volatile("cp.async.wait_group 0;\n");
    __syncthreads();
    {
        const __nv_bfloat16* Wu = Ws + (32 % NSLOT) * SLOT_E;
        #pragma unroll
        for (int j = 0; j < 4; ++j) {               // k' = j*8 .. j*8+7
            float c0[2], c1[2], c2[2], c3[2];
            #pragma unroll
            for (int rg = 0; rg < 2; ++rg) { c0[rg]=0.f; c1[rg]=0.f; c2[rg]=0.f; c3[rg]=0.f; }
            #pragma unroll
            for (int es = 0; es < 4; ++es) {
                const uint2 bb = *(const uint2*)&Wu[(j * 8 + g) * SWW + es * 16 + 4 * t4];
                #pragma unroll
                for (int rg = 0; rg < 2; ++rg)
                    MMA(c0[rg], c1[rg], c2[rg], c3[rg],
                        aF[es][rg][0], aF[es][rg][1], aF[es][rg][2], aF[es][rg][3],
                        bb.x, bb.y);
            }
            const int k0 = j * 8 + 2 * t4;
            #pragma unroll
            for (int rg = 0; rg < 2; ++rg) {
                const int r = base + rg * 16 + g;
                float cc;
                cc = fmaf(Ps[r       * PSW + k0],     c0[rg],
                     fmaf(Ps[r       * PSW + k0 + 1], c1[rg], 0.f));
                cc = fmaf(Ps[(r + 8) * PSW + k0],     c2[rg], cc);
                cc = fmaf(Ps[(r + 8) * PSW + k0 + 1], c3[rg], cc);
                accc[rg] += cc;
            }
        }
    }

    // deterministic combine of private partials
    float acc_sq = (accs[0][0] + accs[0][1]) + (accs[1][0] + accs[1][1]);
    float acc_cr = accc[0] + accc[1];
    float acc = fmaf(-0.5f, acc_sq, acc_cr);

    // constant part: row tid
    {
        float c = 0.f;
        #pragma unroll
        for (int kk = 0; kk < 32; ++kk)
            c = fmaf(Ps[tid * PSW + kk], nhc[kk], c);
        acc += c;
    }

    // deterministic block reduction
    red[tid] = acc;
    __syncthreads();
    #pragma unroll
    for (int st = 128; st > 0; st >>= 1) {
        if (tid < st) red[tid] += red[tid + st];
        __syncthreads();
    }
    if (tid == 0) g_part[gbid] = red[0];

    // ---- last block overall: final reduce + reset
    if (tid == 0) {
        __threadfence();
        const int old = atomicAdd(&g_done, 1);
        flg[0] = (old == total - 1) ? 1 : 0;
    }
    __syncthreads();
    if (flg[0]) {
        __threadfence();
        float a = 0.f;
        for (int i = tid; i < nb; i += 256) a += g_part[i];
        red[tid] = a;
        __syncthreads();
        #pragma unroll
        for (int st = 128; st > 0; st >>= 1) {
            if (tid < st) red[tid] += red[tid + st];
            __syncthreads();
        }
        if (tid == 0) {
            out[0] = fabsf(red[0]);
            g_done  = 0;
            g_ready = 0;
        }
    }
}

// ---------------- launch ----------------
extern "C" void kernel_launch(void* const* d_in, const int* in_sizes, int n_in,
                              void* d_out, int out_size)
{
    const float* emb    = (const float*)d_in[0];   // (500000, 64)
    const float* cen    = (const float*)d_in[1];   // (32, 64)
    const float* cov    = (const float*)d_in[2];   // (32, 64, 64)
    const float* pi     = (const float*)d_in[3];   // (500000, 32)
    const int*   labels = (const int*)d_in[4];     // (B,)
    const int B  = in_sizes[4];
    const int nb = B / 256;

    static int configured = 0;
    if (!configured) {
        cudaFuncSetAttribute(fused_kernel, cudaFuncAttributeMaxDynamicSharedMemorySize,
                             SMEM_TOTAL);
        configured = 1;
    }

    fused_kernel<<<nb + 32, 256, SMEM_TOTAL>>>(emb, cen, cov, pi, labels,
                                               (float*)d_out);
}

// round 17
// speedup vs baseline: 1.0681x; 1.0005x over previous
#include <cuda_runtime.h>
#include <cuda_bf16.h>
#include <math.h>

// ---------------- device scratch (no allocations allowed) ----------------
// g_Wb rows are PERMUTED within each 16-element block:
//   new position 16*blk + 4*t4 + 2*h + b  <-  old element 16*blk + 2*t4 + b + 8*h
// so thread (g,t4)'s two MMA B-operand words are one contiguous 8B load.
__device__ __nv_bfloat16 g_Wb[33 * 64 * 64]; // [k][d][pe]; slot 32 = U (cross)
__device__ float g_nhc[32];                  // -0.5*(D*log2pi + logdet + tau)
__device__ float g_part[4096];               // per-block partial sums
__device__ int   g_ready;                    // # components prepped
__device__ int   g_done;                     // # blocks finished

#define LOG2PI 1.8378770664093453f
#define SW  72     // Xs bf16 stride (front phase; conflict-free aF LDS.32)
#define SWW 80     // W slot bf16 row stride (160B: conflict-free LDS.64)
#define PSW 36     // Ps float stride (144B, 16B-aligned for cp.async)
#define SLOT_E (64 * SWW)   // 5120 bf16 = 10240 B per W slot
#define NSLOT 6

// dynamic smem layout (bytes).
#define OFF_XS   0
#define OFF_WS   0
#define OFF_PS   61440                      // float [256*PSW]          36864
#define OFF_NHC  98304                      // float [32]                 128
#define OFF_LBL  98432                      // int   [256]               1024
#define OFF_RED  99456                      // float [256]               1024
#define OFF_FLG  100480                     // int                         16
#define SMEM_TOTAL 100496

__device__ __forceinline__ void cp_async16(void* dst, const void* src) {
    unsigned a = (unsigned)__cvta_generic_to_shared(dst);
    asm volatile("cp.async.ca.shared.global [%0], [%1], 16;\n"
                 :: "r"(a), "l"(src) : "memory");
}

#define MMA(c0,c1,c2,c3,a0,a1,a2,a3,b0,b1)                                   \
    asm volatile(                                                            \
        "mma.sync.aligned.m16n8k16.row.col.f32.bf16.bf16.f32 "               \
        "{%0,%1,%2,%3}, {%4,%5,%6,%7}, {%8,%9}, {%0,%1,%2,%3};\n"            \
        : "+f"(c0), "+f"(c1), "+f"(c2), "+f"(c3)                             \
        : "r"(a0), "r"(a1), "r"(a2), "r"(a3), "r"(b0), "r"(b1))

// ---------------- prep: PIPELINED panel Cholesky (256 threads) ----------------
__device__ void do_prep(int k, const float* __restrict__ cov,
                        const float* __restrict__ cen, char* smem_raw, int tid)
{
    float* A    = (float*)smem_raw;          // 64*65
    float* Li   = A  + 64 * 65;              // 64*65
    float* rd   = Li + 64 * 65;              // 64
    float* dl   = rd + 64;                   // 64
    float* tsm  = dl + 64;                   // 64

    const int l  = tid & 31;
    const int wp = tid >> 5;

    for (int idx = tid; idx < 4096; idx += 256)
        A[(idx >> 6) * 65 + (idx & 63)] = cov[k * 4096 + idx];
    __syncthreads();

    #pragma unroll 1
    for (int s = 0; s < 8; ++s) {
        const int c0 = s * 8;
        if (wp == 0) {
            const int r0 = c0 + l, r1 = c0 + 32 + l;
            const bool act0 = (r0 < 64), act1 = (r1 < 64);
            float a0[8], a1[8];
            #pragma unroll
            for (int m = 0; m < 8; ++m) {
                a0[m] = act0 ? A[r0 * 65 + c0 + m] : 0.f;
                a1[m] = act1 ? A[r1 * 65 + c0 + m] : 0.f;
            }
            if (s > 0) {
                const int q0 = c0 - 8;
                float lr0[8], lr1[8];
                #pragma unroll
                for (int i = 0; i < 8; ++i) {
                    lr0[i] = act0 ? A[r0 * 65 + q0 + i] : 0.f;
                    lr1[i] = act1 ? A[r1 * 65 + q0 + i] : 0.f;
                }
                #pragma unroll
                for (int m = 0; m < 8; ++m) {
                    float lc[8];
                    #pragma unroll
                    for (int i = 0; i < 8; ++i)
                        lc[i] = A[(c0 + m) * 65 + q0 + i];
                    #pragma unroll
                    for (int i = 0; i < 8; ++i) {
                        a0[m] -= lr0[i] * lc[i];
                        a1[m] -= lr1[i] * lc[i];
                    }
                }
            }
            #pragma unroll
            for (int jj = 0; jj < 8; ++jj) {
                const float d = __shfl_sync(0xffffffffu, a0[jj], jj);
                const float rs = rsqrtf(d);
                if (act0 && l >= jj) a0[jj] *= rs;
                if (act1)            a1[jj] *= rs;
                float lv[8];
                #pragma unroll
                for (int m = jj + 1; m < 8; ++m)
                    lv[m] = __shfl_sync(0xffffffffu, a0[jj], m);
                #pragma unroll
                for (int m = jj + 1; m < 8; ++m) {
                    if (act0 && l > jj) a0[m] -= a0[jj] * lv[m];
                    if (act1)           a1[m] -= a1[jj] * lv[m];
                }
            }
            #pragma unroll
            for (int m = 0; m < 8; ++m) {
                if (act0) A[r0 * 65 + c0 + m] = a0[m];
                if (act1) A[r1 * 65 + c0 + m] = a1[m];
            }
        } else if (s > 0) {
            const int cbase = c0 + 8;
            if (cbase < 64) {
                const int q0 = c0 - 8;
                const int ht = tid - 32;
                const int r  = cbase + (ht >> 2);
                const int cq = ht & 3;
                if (r < 64) {
                    float pr[8];
                    #pragma unroll
                    for (int i = 0; i < 8; ++i) pr[i] = A[r * 65 + q0 + i];
                    for (int c = cbase + cq; c <= r; c += 4) {
                        float v = A[r * 65 + c];
                        #pragma unroll
                        for (int i = 0; i < 8; ++i)
                            v -= pr[i] * A[c * 65 + q0 + i];
                        A[r * 65 + c] = v;
                    }
                }
            }
        }
        __syncthreads();
    }

    if (tid < 64) {
        const float dii = A[tid * 65 + tid];
        dl[tid] = 2.f * logf(dii);
        rd[tid] = 1.0f / dii;
    }
    __syncthreads();

    // forward substitution: 8 warps x 8 columns each
    {
        const int r0 = l, r1 = l + 32;
        const int c0 = wp * 8;
        float v0[8], v1[8];
        #pragma unroll
        for (int j = 0; j < 8; ++j) {
            v0[j] = (r0 == c0 + j) ? 1.f : 0.f;
            v1[j] = (r1 == c0 + j) ? 1.f : 0.f;
        }
        for (int m = 0; m < 64; ++m) {
            const float lr0 = (r0 > m) ? A[r0 * 65 + m] : 0.f;
            const float lr1 = (r1 > m) ? A[r1 * 65 + m] : 0.f;
            const float rdm = rd[m];
            const int   src = m & 31;
            const bool  lo  = (m < 32);
            #pragma unroll
            for (int j = 0; j < 8; ++j) {
                const float resid = lo ? v0[j] : v1[j];
                const float ym = __shfl_sync(0xffffffffu, resid, src) * rdm;
                v0[j] -= lr0 * ym;
                v1[j] -= lr1 * ym;
                if (l == src) Li[m * 65 + c0 + j] = ym;
            }
        }
    }
    __syncthreads();

    // t = Linv * c (fp32), 4-way partials
    if (tid < 64) {
        float s0 = 0.f, s1 = 0.f, s2 = 0.f, s3 = 0.f;
        int e = 0;
        for (; e + 3 <= tid; e += 4) {
            s0 += Li[tid * 65 + e]     * cen[k * 64 + e];
            s1 += Li[tid * 65 + e + 1] * cen[k * 64 + e + 1];
            s2 += Li[tid * 65 + e + 2] * cen[k * 64 + e + 2];
            s3 += Li[tid * 65 + e + 3] * cen[k * 64 + e + 3];
        }
        for (; e <= tid; ++e) s0 += Li[tid * 65 + e] * cen[k * 64 + e];
        tsm[tid] = (s0 + s1) + (s2 + s3);
    }
    __syncthreads();

    // u = Linv^T t (bf16 row k of cross matrix), PERMUTED column position
    if (tid < 64) {
        const int e = tid;
        float s0 = 0.f, s1 = 0.f, s2 = 0.f, s3 = 0.f;
        int d = e;
        for (; d + 3 < 64; d += 4) {
            s0 += Li[d * 65 + e]       * tsm[d];
            s1 += Li[(d + 1) * 65 + e] * tsm[d + 1];
            s2 += Li[(d + 2) * 65 + e] * tsm[d + 2];
            s3 += Li[(d + 3) * 65 + e] * tsm[d + 3];
        }
        for (; d < 64; ++d) s0 += Li[d * 65 + e] * tsm[d];
        const int le = e & 15;
        const int t4 = (le & 7) >> 1, b = le & 1, h = le >> 3;
        const int pe = (e & ~15) + 4 * t4 + 2 * h + b;
        g_Wb[32 * 4096 + k * 64 + pe] = __float2bfloat16_rn((s0 + s1) + (s2 + s3));
    }
    if (tid == 0) {
        float ld = 0.f, tau = 0.f;
        #pragma unroll 4
        for (int m = 0; m < 64; ++m) { ld += dl[m]; tau += tsm[m] * tsm[m]; }
        g_nhc[k] = -0.5f * (64.f * LOG2PI + ld + tau);
    }
    // bf16 W, permuted within each 16-element block
    #pragma unroll 4
    for (int idx = tid; idx < 4096; idx += 256) {
        const int d = idx >> 6, pe = idx & 63;
        const int lp = pe & 15;
        const int t4 = lp >> 2, r = lp & 3;
        const int oe = (pe & ~15) + 2 * t4 + (r & 1) + (r >> 1) * 8;
        const float v = (oe <= d) ? Li[d * 65 + oe] : 0.f;
        g_Wb[k * 4096 + idx] = __float2bfloat16_rn(v);
    }
}

// ---------------- single fused kernel -----------------------------------------
// grid = 32 prep blocks + B/256 GEMM blocks; block = 256 threads (8 warps)
__global__ void __launch_bounds__(256, 2) fused_kernel(const float* __restrict__ emb,
                                                       const float* __restrict__ cen,
                                                       const float* __restrict__ cov,
                                                       const float* __restrict__ pi,
                                                       const int* __restrict__ labels,
                                                       float* __restrict__ out)
{
    extern __shared__ char smem[];
    __nv_bfloat16* Xs  = (__nv_bfloat16*)(smem + OFF_XS);   // front phase only
    __nv_bfloat16* Ws  = (__nv_bfloat16*)(smem + OFF_WS);   // [6][SLOT_E] ring
    float* Ps  = (float*)(smem + OFF_PS);
    float* nhc = (float*)(smem + OFF_NHC);
    int*   lbl = (int*)  (smem + OFF_LBL);
    float* red = (float*)(smem + OFF_RED);
    int*   flg = (int*)  (smem + OFF_FLG);

    const int tid   = threadIdx.x;
    const int total = gridDim.x;         // nb + 32
    const int nb    = total - 32;

    // =================== prep blocks: prep only, then exit =====================
    if (blockIdx.x < 32) {
        do_prep(blockIdx.x, cov, cen, smem, tid);
        __syncthreads();
        if (tid == 0) {
            __threadfence();
            atomicAdd(&g_ready, 1);
            __threadfence();
            const int old = atomicAdd(&g_done, 1);
            flg[0] = (old == total - 1) ? 1 : 0;
        }
        __syncthreads();
        if (flg[0]) {
            __threadfence();
            float a = 0.f;
            for (int i = tid; i < nb; i += 256) a += g_part[i];
            red[tid] = a;
            __syncthreads();
            #pragma unroll
            for (int st = 128; st > 0; st >>= 1) {
                if (tid < st) red[tid] += red[tid + st];
                __syncthreads();
            }
            if (tid == 0) { out[0] = fabsf(red[0]); g_done = 0; g_ready = 0; }
        }
        return;
    }

    // =================== GEMM blocks ==========================================
    const int gbid = blockIdx.x - 32;
    const int b0   = gbid * 256;

    const int w    = tid >> 5;        // warp 0..7 -> rows w*32 .. w*32+31
    const int lane = tid & 31;
    const int g    = lane >> 2;
    const int t4   = lane & 3;
    const int base = w * 32;

    // ---- WARP-LOCAL front phase (no block barriers) ----
    lbl[base + lane] = labels[b0 + base + lane];
    __syncwarp();

    #pragma unroll
    for (int it = 0; it < 8; ++it) {
        const int idx = lane + it * 32;
        const int row = base + (idx >> 3), c8 = idx & 7;
        cp_async16(&Ps[row * PSW + c8 * 4],
                   pi + (size_t)lbl[row] * 32 + c8 * 4);
    }
    asm volatile("cp.async.commit_group;\n");

    {
        const int f4 = lane & 15, rh = lane >> 4;
        #pragma unroll 8
        for (int it = 0; it < 16; ++it) {
            const int row = base + rh + it * 2;
            const float4 v = *(const float4*)(emb + (size_t)lbl[row] * 64 + f4 * 4);
            __nv_bfloat162* p = (__nv_bfloat162*)&Xs[row * SW + f4 * 4];
            p[0] = __nv_bfloat162(__float2bfloat16_rn(v.x), __float2bfloat16_rn(v.y));
            p[1] = __nv_bfloat162(__float2bfloat16_rn(v.z), __float2bfloat16_rn(v.w));
        }
    }
    __syncwarp();

    // A fragments: loaded ONCE from this warp's Xs rows (32 regs)
    unsigned aF[4][2][4];
    #pragma unroll
    for (int es = 0; es < 4; ++es) {
        const int e0 = es * 16 + 2 * t4;
        #pragma unroll
        for (int rg = 0; rg < 2; ++rg) {
            const int r = base + rg * 16 + g;
            aF[es][rg][0] = *(const unsigned*)&Xs[r       * SW + e0];
            aF[es][rg][1] = *(const unsigned*)&Xs[(r + 8) * SW + e0];
            aF[es][rg][2] = *(const unsigned*)&Xs[r       * SW + e0 + 8];
            aF[es][rg][3] = *(const unsigned*)&Xs[(r + 8) * SW + e0 + 8];
        }
    }
    __syncthreads();   // all warps past Xs reads: W ring may overwrite it

    // ---- wait for all components (cheap volatile poll)
    if (tid == 0) {
        while (*(volatile int*)&g_ready < 32) { __nanosleep(100); }
    }
    __syncthreads();
    __threadfence();
    if (tid < 32) nhc[tid] = g_nhc[tid];

    auto prefetch = [&](int k) {
        if (k > 32) return;
        const uint4* src = (const uint4*)(g_Wb + k * 4096);
        __nv_bfloat16* dst = Ws + (k % NSLOT) * SLOT_E;
        #pragma unroll
        for (int it = 0; it < 2; ++it) {
            const int idx = tid + it * 256;
            cp_async16(&dst[(idx >> 3) * SWW + (idx & 7) * 8], &src[idx]);
        }
    };

    // init: 2 pairs in flight
    prefetch(0); prefetch(1);
    asm volatile("cp.async.commit_group;\n");
    prefetch(2); prefetch(3);
    asm volatile("cp.async.commit_group;\n");

    float accs[2][2];
    #pragma unroll
    for (int rg = 0; rg < 2; ++rg) { accs[rg][0] = 0.f; accs[rg][1] = 0.f; }
    float accc[2] = {0.f, 0.f};

    // per-pair compute: k0 and k1 INTERLEAVED in one j-loop (4 independent
    // MMA chains per warp; k0's q-tail overlaps k1's MMA issue)
    auto mainK2 = [&](int k0, int k1) {
        const __nv_bfloat16* W0 = Ws + (k0 % NSLOT) * SLOT_E;
        const __nv_bfloat16* W1 = Ws + (k1 % NSLOT) * SLOT_E;
        float qA0[2] = {0.f, 0.f}, qA1[2] = {0.f, 0.f};   // k0: [rg] halves
        float qB0[2] = {0.f, 0.f}, qB1[2] = {0.f, 0.f};   // k1
        #pragma unroll
        for (int j = 0; j < 8; ++j) {
            float cA[2][4], cB[2][4];
            #pragma unroll
            for (int rg = 0; rg < 2; ++rg)
                #pragma unroll
                for (int i = 0; i < 4; ++i) { cA[rg][i] = 0.f; cB[rg][i] = 0.f; }
            const int esn = j / 2 + 1;     // triangular skip (both k's)
            #pragma unroll
            for (int es = 0; es < esn; ++es) {
                const int off = (j * 8 + g) * SWW + es * 16 + 4 * t4;
                const uint2 b0 = *(const uint2*)&W0[off];
                const uint2 b1 = *(const uint2*)&W1[off];
                #pragma unroll
                for (int rg = 0; rg < 2; ++rg) {
                    MMA(cA[rg][0], cA[rg][1], cA[rg][2], cA[rg][3],
                        aF[es][rg][0], aF[es][rg][1], aF[es][rg][2], aF[es][rg][3],
                        b0.x, b0.y);
                    MMA(cB[rg][0], cB[rg][1], cB[rg][2], cB[rg][3],
                        aF[es][rg][0], aF[es][rg][1], aF[es][rg][2], aF[es][rg][3],
                        b1.x, b1.y);
                }
            }
            #pragma unroll
            for (int rg = 0; rg < 2; ++rg) {
                qA0[rg] = fmaf(cA[rg][0], cA[rg][0], qA0[rg]);
                qA0[rg] = fmaf(cA[rg][1], cA[rg][1], qA0[rg]);
                qA1[rg] = fmaf(cA[rg][2], cA[rg][2], qA1[rg]);
                qA1[rg] = fmaf(cA[rg][3], cA[rg][3], qA1[rg]);
                qB0[rg] = fmaf(cB[rg][0], cB[rg][0], qB0[rg]);
                qB0[rg] = fmaf(cB[rg][1], cB[rg][1], qB0[rg]);
                qB1[rg] = fmaf(cB[rg][2], cB[rg][2], qB1[rg]);
                qB1[rg] = fmaf(cB[rg][3], cB[rg][3], qB1[rg]);
            }
        }
        #pragma unroll
        for (int rg = 0; rg < 2; ++rg) {
            const int r = base + rg * 16 + g;
            accs[rg][0] = fmaf(Ps[r       * PSW + k0], qA0[rg], accs[rg][0]);
            accs[rg][1] = fmaf(Ps[(r + 8) * PSW + k0], qA1[rg], accs[rg][1]);
            accs[rg][0] = fmaf(Ps[r       * PSW + k1], qB0[rg], accs[rg][0]);
            accs[rg][1] = fmaf(Ps[(r + 8) * PSW + k1], qB1[rg], accs[rg][1]);
        }
    };

    // ---- pair loop: ONE barrier per 2 k's; prefetch 2 pairs ahead
    #pragma unroll 1
    for (int kk = 0; kk < 32; kk += 2) {
        asm volatile("cp.async.wait_group 1;\n");   // group for pair kk landed
        __syncthreads();                            // visibility + old slots free
        prefetch(kk + 4);
        prefetch(kk + 5);
        asm volatile("cp.async.commit_group;\n");
        mainK2(kk, kk + 1);
    }

    // ---- final: cross terms  cross[b][k'] = x_b . u_k'  (slot 32%6 = 2)
    asm volatile("cp.async.wait_group 0;\n");
    __syncthreads();
    {
        const __nv_bfloat16* Wu = Ws + (32 % NSLOT) * SLOT_E;
        #pragma unroll
        for (int j = 0; j < 4; ++j) {               // k' = j*8 .. j*8+7
            float c0[2], c1[2], c2[2], c3[2];
            #pragma unroll
            for (int rg = 0; rg < 2; ++rg) { c0[rg]=0.f; c1[rg]=0.f; c2[rg]=0.f; c3[rg]=0.f; }
            #pragma unroll
            for (int es = 0; es < 4; ++es) {
                const uint2 bb = *(const uint2*)&Wu[(j * 8 + g) * SWW + es * 16 + 4 * t4];
                #pragma unroll
                for (int rg = 0; rg < 2; ++rg)
                    MMA(c0[rg], c1[rg], c2[rg], c3[rg],
                        aF[es][rg][0], aF[es][rg][1], aF[es][rg][2], aF[es][rg][3],
                        bb.x, bb.y);
            }
            const int k0 = j * 8 + 2 * t4;
            #pragma unroll
            for (int rg = 0; rg < 2; ++rg) {
                const int r = base + rg * 16 + g;
                float cc;
                cc = fmaf(Ps[r       * PSW + k0],     c0[rg],
                     fmaf(Ps[r       * PSW + k0 + 1], c1[rg], 0.f));
                cc = fmaf(Ps[(r + 8) * PSW + k0],     c2[rg], cc);
                cc = fmaf(Ps[(r + 8) * PSW + k0 + 1], c3[rg], cc);
                accc[rg] += cc;
            }
        }
    }

    // deterministic combine of private partials
    float acc_sq = (accs[0][0] + accs[0][1]) + (accs[1][0] + accs[1][1]);
    float acc_cr = accc[0] + accc[1];
    float acc = fmaf(-0.5f, acc_sq, acc_cr);

    // constant part: row tid
    {
        float c = 0.f;
        #pragma unroll
        for (int kk = 0; kk < 32; ++kk)
            c = fmaf(Ps[tid * PSW + kk], nhc[kk], c);
        acc += c;
    }

    // deterministic block reduction
    red[tid] = acc;
    __syncthreads();
    #pragma unroll
    for (int st = 128; st > 0; st >>= 1) {
        if (tid < st) red[tid] += red[tid + st];
        __syncthreads();
    }
    if (tid == 0) g_part[gbid] = red[0];

    // ---- last block overall: final reduce + reset
    if (tid == 0) {
        __threadfence();
        const int old = atomicAdd(&g_done, 1);
        flg[0] = (old == total - 1) ? 1 : 0;
    }
    __syncthreads();
    if (flg[0]) {
        __threadfence();
        float a = 0.f;
        for (int i = tid; i < nb; i += 256) a += g_part[i];
        red[tid] = a;
        __syncthreads();
        #pragma unroll
        for (int st = 128; st > 0; st >>= 1) {
            if (tid < st) red[tid] += red[tid + st];
            __syncthreads();
        }
        if (tid == 0) {
            out[0] = fabsf(red[0]);
            g_done  = 0;
            g_ready = 0;
        }
    }
}

// ---------------- launch ----------------
extern "C" void kernel_launch(void* const* d_in, const int* in_sizes, int n_in,
                              void* d_out, int out_size)
{
    const float* emb    = (const float*)d_in[0];   // (500000, 64)
    const float* cen    = (const float*)d_in[1];   // (32, 64)
    const float* cov    = (const float*)d_in[2];   // (32, 64, 64)
    const float* pi     = (const float*)d_in[3];   // (500000, 32)
    const int*   labels = (const int*)d_in[4];     // (B,)
    const int B  = in_sizes[4];
    const int nb = B / 256;

    static int configured = 0;
    if (!configured) {
        cudaFuncSetAttribute(fused_kernel, cudaFuncAttributeMaxDynamicSharedMemorySize,
                             SMEM_TOTAL);
        configured = 1;
    }

    fused_kernel<<<nb + 32, 256, SMEM_TOTAL>>>(emb, cen, cov, pi, labels,
                                               (float*)d_out);
}